// round 4
// baseline (speedup 1.0000x reference)
#include <cuda_runtime.h>
#include <math.h>

#define BB  32
#define VV  512
#define TT  12
#define FINC 2
#define DGC 20
#define CHC 16
#define HORC 12
#define NLC 8
#define EPSC 0.3f
#define RFC 13

// -------------------- device scratch (static, no allocation) --------------------
__device__ float g_XA[VV*BB*CHC*13];
__device__ float g_XB[VV*BB*CHC*13];
__device__ float g_XG[VV*BB*CHC*13];
__device__ float g_P [VV*BB*CHC*13];
__device__ float g_Q [VV*BB*CHC*13];
__device__ float g_skip[VV*BB*CHC];
__device__ float g_real[BB*VV*DGC];
__device__ float g_img [BB*VV*DGC];
__device__ float g_feat[BB*VV*60];
__device__ float g_adj [VV*VV];
__device__ float g_ct[VV], g_st[VV];
__device__ float g_Cw[DGC*24], g_Sw[DGC*24];
__device__ float g_wc[VV*60], g_bc[VV];
__device__ float g_WX[NLC*CHC*CHC], g_WP[NLC*CHC*CHC], g_WQ[NLC*CHC*CHC];
__device__ float g_bnsc[NLC*CHC], g_bnsh[NLC*CHC];

__device__ __forceinline__ float sigm(float x) { return 1.f / (1.f + expf(-x)); }

// -------------------- setup: fold constants --------------------
__global__ void setup_kernel(const float* __restrict__ lin_W,
                             const float* __restrict__ fc1_W, const float* __restrict__ fc1_b,
                             const float* __restrict__ fc2_W, const float* __restrict__ fc2_b,
                             const float* __restrict__ fc3_W, const float* __restrict__ fc3_b,
                             const float* __restrict__ gconv_W,
                             const float* __restrict__ bn_gamma, const float* __restrict__ bn_beta,
                             const float* __restrict__ bn_mean, const float* __restrict__ bn_var) {
    int idx0 = blockIdx.x * blockDim.x + threadIdx.x;
    int stride = gridDim.x * blockDim.x;
    const double PI = 3.14159265358979323846;
    for (int i = idx0; i < 512; i += stride) {
        double a = 2.0 * PI * (double)i / 512.0;
        g_ct[i] = (float)cos(a); g_st[i] = (float)sin(a);
    }
    for (int i = idx0; i < DGC*24; i += stride) {
        int d = i / 24, n = i % 24;
        float cs = 0.f, sn = 0.f;
        for (int j = 0; j < 24; j++) {
            double a = 2.0 * PI * (double)((j*n) % 24) / 24.0;
            cs += lin_W[d*24+j] * (float)cos(a);
            sn += lin_W[d*24+j] * (float)(-sin(a));
        }
        g_Cw[i] = cs; g_Sw[i] = sn;
    }
    for (int i = idx0; i < VV*60; i += stride) {
        int w = i / 60, j = i % 60;
        float v = (j < 20) ? fc1_W[w*20+j] : (j < 40) ? fc2_W[w*20+j-20] : fc3_W[w*20+j-40];
        g_wc[i] = v;
    }
    for (int i = idx0; i < VV; i += stride) g_bc[i] = fc1_b[i] + fc2_b[i] + fc3_b[i];
    for (int i = idx0; i < NLC*256; i += stride) {
        int L = i >> 8, ci = i & 15, co = (i >> 4) & 15;
        const float* G = gconv_W + (size_t)(L*16 + co)*64;
        float w1 = G[ci], w2 = G[16+ci], w3 = G[32+ci], w4 = G[48+ci];
        g_WX[i] = EPSC*(w1+w3) + EPSC*EPSC*(w2+w4);
        g_WP[i] = (w1 - w3) + 2.f*EPSC*(w2 - w4);
        g_WQ[i] = w2 + w4;
    }
    for (int i = idx0; i < NLC*CHC; i += stride) {
        float sc = bn_gamma[i] / sqrtf(bn_var[i] + 1e-5f);
        g_bnsc[i] = sc;
        g_bnsh[i] = bn_beta[i] - bn_mean[i]*sc;
    }
}

// -------------------- DFT(24) folded into linear layer + Am/S features --------------------
__global__ void fftlin_kernel(const float* __restrict__ input, const float* __restrict__ lin_b) {
    int bv = blockIdx.x; int b = bv >> 9, v = bv & 511;
    __shared__ float xr[24];
    int tid = threadIdx.x;
    if (tid < 24) {
        int t = tid >> 1, f = tid & 1;
        xr[tid] = input[(((size_t)t*BB + b)*VV + v)*FINC + f];
    }
    __syncthreads();
    if (tid < DGC) {
        float re = lin_b[tid], im = lin_b[tid];
        #pragma unroll
        for (int n = 0; n < 24; n++) {
            re += xr[n] * g_Cw[tid*24+n];
            im += xr[n] * g_Sw[tid*24+n];
        }
        int base = (b*VV + v)*DGC + tid;
        g_real[base] = re; g_img[base] = im;
        int fb = (b*VV + v)*60 + tid;
        g_feat[fb + 20] = sqrtf(re*re + im*im);
        g_feat[fb + 40] = atanf(re / (im + 1e-4f));
    }
}

// -------------------- irfft over the V axis (n=512, crop to 257 coeffs) --------------------
__global__ void irfft_kernel() {
    __shared__ float ct[512], st[512];
    __shared__ float partial[160];
    int bm = blockIdx.x; int b = bm >> 9, m = bm & 511;
    int tid = threadIdx.x;  // 160
    for (int i = tid; i < 512; i += 160) { ct[i] = g_ct[i]; st[i] = g_st[i]; }
    __syncthreads();
    int d = tid % 20, kg = tid / 20;  // kg 0..7
    const float* R = g_real + (size_t)b * VV * DGC;
    const float* I = g_img  + (size_t)b * VV * DGC;
    float s = 0.f;
    for (int k = 1 + kg; k <= 255; k += 8) {
        int a = (k * m) & 511;
        s += R[k*20 + d] * ct[a] - I[k*20 + d] * st[a];
    }
    s *= 2.f;
    if (kg == 0) {
        s += R[d];
        s += ((m & 1) ? -1.f : 1.f) * R[256*20 + d];
    }
    partial[tid] = s;
    __syncthreads();
    if (tid < 20) {
        float tot = 0.f;
        #pragma unroll
        for (int g = 0; g < 8; g++) tot += partial[g*20 + tid];
        g_feat[((size_t)b*VV + m)*60 + tid] = tot * (1.f/512.f);
    }
}

// -------------------- adj = sigmoid(mean_b sigmoid((F·Wc + bc)/3)) --------------------
__global__ __launch_bounds__(256) void adj_kernel() {
    __shared__ float Ws[64][61];
    __shared__ float Fs[32][61];
    __shared__ float bcs[64];
    int bw = blockIdx.x * 64, bv = blockIdx.y * 32;
    int tid = threadIdx.x;
    for (int idx = tid; idx < 64*60; idx += 256)
        Ws[idx/60][idx%60] = g_wc[(bw + idx/60)*60 + idx%60];
    if (tid < 64) bcs[tid] = g_bc[bw + tid];
    float acc[8] = {0,0,0,0,0,0,0,0};
    int w = tid & 63, vg = tid >> 6;  // vg 0..3
    for (int b = 0; b < BB; b++) {
        __syncthreads();
        for (int idx = tid; idx < 32*60; idx += 256)
            Fs[idx/60][idx%60] = g_feat[((size_t)b*VV + bv + idx/60)*60 + idx%60];
        __syncthreads();
        #pragma unroll
        for (int s = 0; s < 8; s++) {
            int vi = vg + 4*s;
            float d = bcs[w];
            #pragma unroll
            for (int j = 0; j < 60; j++) d += Fs[vi][j] * Ws[w][j];
            acc[s] += sigm(d * (1.f/3.f));
        }
    }
    #pragma unroll
    for (int s = 0; s < 8; s++)
        g_adj[(size_t)(bv + vg + 4*s)*VV + bw + w] = sigm(acc[s] * (1.f/BB));
}

// -------------------- start 1x1 conv (with left time pad) + zero skip --------------------
__global__ void start_kernel(const float* __restrict__ input,
                             const float* __restrict__ start_W, const float* __restrict__ start_b) {
    int vb = blockIdx.x; int v = vb >> 5, b = vb & 31;
    int c = threadIdx.x, l = threadIdx.y;
    __shared__ float xin[FINC][13];
    int tid = l*16 + c;
    if (tid < FINC*13) {
        int f = tid / 13, ll = tid % 13;
        xin[f][ll] = (ll == 0) ? 0.f : input[((((size_t)(ll-1))*BB + b)*VV + v)*FINC + f];
    }
    __syncthreads();
    float val = start_b[c] + start_W[c*2+0]*xin[0][l] + start_W[c*2+1]*xin[1][l];
    g_XA[(((size_t)v*BB + b)*CHC + c)*13 + l] = val;
    if (l == 0) g_skip[((size_t)v*BB + b)*CHC + c] = 0.f;
}

// -------------------- gated temporal conv + skip tail accumulation --------------------
__global__ void gate_skip_kernel(int layer, int Lin, int Lout, int dil, int flip,
                                 const float* __restrict__ filt_W, const float* __restrict__ filt_b,
                                 const float* __restrict__ gate_W, const float* __restrict__ gate_b,
                                 const float* __restrict__ skip_W, const float* __restrict__ skip_b) {
    const float* X = flip ? g_XB : g_XA;
    int vb = blockIdx.x; int v = vb >> 5, b = vb & 31;
    __shared__ float xs[CHC][13];
    __shared__ float xg[CHC][12];
    __shared__ float fw[CHC*CHC*2], gw[CHC*CHC*2], sw[CHC*CHC];
    int c = threadIdx.x, l = threadIdx.y;
    int tid = l*16 + c;
    for (int idx = tid; idx < 512; idx += 208) { fw[idx] = filt_W[layer*512+idx]; gw[idx] = gate_W[layer*512+idx]; }
    for (int idx = tid; idx < 256; idx += 208) sw[idx] = skip_W[layer*256+idx];
    const float* xp = X + ((size_t)(v*BB + b)*CHC) * Lin;
    if (l < Lin) xs[c][l] = xp[c*Lin + l];
    __syncthreads();
    if (l < Lout) {
        float f = filt_b[layer*16+c], g = gate_b[layer*16+c];
        #pragma unroll
        for (int ci = 0; ci < CHC; ci++) {
            float x0 = xs[ci][l], x1 = xs[ci][l+dil];
            f += fw[(c*16+ci)*2]*x0 + fw[(c*16+ci)*2+1]*x1;
            g += gw[(c*16+ci)*2]*x0 + gw[(c*16+ci)*2+1]*x1;
        }
        float val = tanhf(f) * sigm(g);
        xg[c][l] = val;
        g_XG[((size_t)(v*BB + b)*CHC + c)*Lout + l] = val;
    }
    __syncthreads();
    if (l == Lout - 1) {
        float s = skip_b[layer*16+c];
        #pragma unroll
        for (int ci = 0; ci < CHC; ci++) s += sw[c*16+ci] * xg[ci][Lout-1];
        g_skip[((size_t)v*BB + b)*CHC + c] += s;
    }
}

// -------------------- diffusion GEMM: C[m,n] = sum_k adj[k,m] * Xin[k,n] --------------------
// which=0: XG -> P ; which=1: P -> Q.  M=K=512, N = 512*Lout (multiple of 128).
__global__ __launch_bounds__(256) void gemm_diff(int which, int N) {
    const float* __restrict__ Xin = which ? g_P : g_XG;
    float* __restrict__ C = which ? g_Q : g_P;
    __shared__ float As[8][128];
    __shared__ float Bs[8][128];
    int bm = blockIdx.y * 128;
    int bn = blockIdx.x * 128;
    int tid = threadIdx.x;
    int tm = (tid >> 4) * 8;   // 0..120
    int tn = (tid & 15) * 8;   // 0..120
    int lr = tid >> 5;         // 0..7
    int lc = (tid & 31) * 4;   // 0..124
    float acc[8][8];
    #pragma unroll
    for (int i = 0; i < 8; i++)
        #pragma unroll
        for (int j = 0; j < 8; j++) acc[i][j] = 0.f;
    for (int k0 = 0; k0 < 512; k0 += 8) {
        *(float4*)&As[lr][lc] = *(const float4*)&g_adj[(size_t)(k0 + lr)*512 + bm + lc];
        *(float4*)&Bs[lr][lc] = *(const float4*)&Xin[(size_t)(k0 + lr)*N + bn + lc];
        __syncthreads();
        #pragma unroll
        for (int kk = 0; kk < 8; kk++) {
            float a[8], x[8];
            *(float4*)(a)   = *(float4*)&As[kk][tm];
            *(float4*)(a+4) = *(float4*)&As[kk][tm+4];
            *(float4*)(x)   = *(float4*)&Bs[kk][tn];
            *(float4*)(x+4) = *(float4*)&Bs[kk][tn+4];
            #pragma unroll
            for (int i = 0; i < 8; i++)
                #pragma unroll
                for (int j = 0; j < 8; j++) acc[i][j] += a[i]*x[j];
        }
        __syncthreads();
    }
    #pragma unroll
    for (int i = 0; i < 8; i++) {
        float4 v0 = make_float4(acc[i][0], acc[i][1], acc[i][2], acc[i][3]);
        float4 v1 = make_float4(acc[i][4], acc[i][5], acc[i][6], acc[i][7]);
        *(float4*)&C[(size_t)(bm + tm + i)*N + bn + tn]     = v0;
        *(float4*)&C[(size_t)(bm + tm + i)*N + bn + tn + 4] = v1;
    }
}

// -------------------- gconv (folded) + residual + BN --------------------
__global__ void combine_kernel(int layer, int Lin, int Lout, int dil, int flip,
                               const float* __restrict__ gconv_b) {
    const float* Xres = flip ? g_XB : g_XA;
    float* Xout = flip ? g_XA : g_XB;
    int vb = blockIdx.x; int v = vb >> 5, b = vb & 31;
    __shared__ float xg[CHC][12], pp[CHC][12], qq[CHC][12];
    __shared__ float wx[256], wp[256], wq[256];
    int c = threadIdx.x, l = threadIdx.y;
    int tid = l*16 + c;
    for (int idx = tid; idx < 256; idx += 208) {
        wx[idx] = g_WX[layer*256+idx];
        wp[idx] = g_WP[layer*256+idx];
        wq[idx] = g_WQ[layer*256+idx];
    }
    size_t base = ((size_t)(v*BB + b)*CHC + c)*Lout;
    if (l < Lout) {
        xg[c][l] = g_XG[base + l];
        pp[c][l] = g_P[base + l];
        qq[c][l] = g_Q[base + l];
    }
    __syncthreads();
    if (l < Lout) {
        float h = gconv_b[layer*16+c];
        #pragma unroll
        for (int ci = 0; ci < CHC; ci++)
            h += wx[c*16+ci]*xg[ci][l] + wp[c*16+ci]*pp[ci][l] + wq[c*16+ci]*qq[ci][l];
        float t = h + Xres[((size_t)(v*BB + b)*CHC + c)*Lin + l + dil];
        Xout[base + l] = t * g_bnsc[layer*16+c] + g_bnsh[layer*16+c];
    }
}

// -------------------- end head --------------------
__global__ void end_kernel(const float* __restrict__ end1_W, const float* __restrict__ end1_b,
                           const float* __restrict__ end2_W, const float* __restrict__ end2_b,
                           float* __restrict__ out) {
    int vb = blockIdx.x; int v = vb >> 5, b = vb & 31;
    __shared__ float o1[16], o2[16];
    int t = threadIdx.x;  // 16
    o1[t] = fmaxf(g_skip[((size_t)v*BB + b)*CHC + t], 0.f);
    __syncthreads();
    float a = end1_b[t];
    #pragma unroll
    for (int ci = 0; ci < 16; ci++) a += end1_W[t*16+ci] * o1[ci];
    o2[t] = fmaxf(a, 0.f);
    __syncthreads();
    if (t < HORC) {
        float r = end2_b[t];
        #pragma unroll
        for (int c = 0; c < 16; c++) r += end2_W[t*16+c] * o2[c];
        out[((size_t)b*HORC + t)*VV + v] = r;
    }
}

__global__ void adjcopy_kernel(float* __restrict__ out) {
    int i = blockIdx.x * 256 + threadIdx.x;
    if (i < VV*VV) out[i] = g_adj[i];
}

// -------------------- launch --------------------
extern "C" void kernel_launch(void* const* d_in, const int* in_sizes, int n_in,
                              void* d_out, int out_size) {
    const float* input    = (const float*)d_in[0];
    const float* start_W  = (const float*)d_in[1];
    const float* start_b  = (const float*)d_in[2];
    const float* filt_W   = (const float*)d_in[3];
    const float* filt_b   = (const float*)d_in[4];
    const float* gate_W   = (const float*)d_in[5];
    const float* gate_b   = (const float*)d_in[6];
    const float* skip_W   = (const float*)d_in[7];
    const float* skip_b   = (const float*)d_in[8];
    const float* gconv_W  = (const float*)d_in[9];
    const float* gconv_b  = (const float*)d_in[10];
    const float* bn_gamma = (const float*)d_in[11];
    const float* bn_beta  = (const float*)d_in[12];
    const float* bn_mean  = (const float*)d_in[13];
    const float* bn_var   = (const float*)d_in[14];
    const float* end1_W   = (const float*)d_in[15];
    const float* end1_b   = (const float*)d_in[16];
    const float* end2_W   = (const float*)d_in[17];
    const float* end2_b   = (const float*)d_in[18];
    const float* lin_W    = (const float*)d_in[19];
    const float* lin_b    = (const float*)d_in[20];
    const float* fc1_W    = (const float*)d_in[21];
    const float* fc1_b    = (const float*)d_in[22];
    const float* fc2_W    = (const float*)d_in[23];
    const float* fc2_b    = (const float*)d_in[24];
    const float* fc3_W    = (const float*)d_in[25];
    const float* fc3_b    = (const float*)d_in[26];
    float* out = (float*)d_out;

    setup_kernel<<<64, 256>>>(lin_W, fc1_W, fc1_b, fc2_W, fc2_b, fc3_W, fc3_b,
                              gconv_W, bn_gamma, bn_beta, bn_mean, bn_var);
    fftlin_kernel<<<BB*VV, 32>>>(input, lin_b);
    irfft_kernel<<<BB*VV, 160>>>();
    adj_kernel<<<dim3(VV/64, VV/32), 256>>>();
    start_kernel<<<VV*BB, dim3(16, 13)>>>(input, start_W, start_b);

    static const int dils[NLC] = {1, 2, 1, 2, 1, 2, 1, 2};
    int L = RFC;
    for (int i = 0; i < NLC; i++) {
        int d = dils[i];
        int Lo = L - d;
        gate_skip_kernel<<<VV*BB, dim3(16, 13)>>>(i, L, Lo, d, i & 1,
                                                  filt_W, filt_b, gate_W, gate_b, skip_W, skip_b);
        int N = BB * CHC * Lo;  // 512 * Lo, multiple of 128
        gemm_diff<<<dim3(N/128, 4), 256>>>(0, N);
        gemm_diff<<<dim3(N/128, 4), 256>>>(1, N);
        combine_kernel<<<VV*BB, dim3(16, 13)>>>(i, L, Lo, d, i & 1, gconv_b);
        L = Lo;
    }
    end_kernel<<<VV*BB, 16>>>(end1_W, end1_b, end2_W, end2_b, out);
    if (out_size >= BB*HORC*VV + VV*VV)
        adjcopy_kernel<<<(VV*VV + 255)/256, 256>>>(out + BB*HORC*VV);
}

// round 9
// speedup vs baseline: 1.0584x; 1.0584x over previous
#include <cuda_runtime.h>
#include <math.h>

#define BB  32
#define VV  512
#define TT  12
#define FINC 2
#define DGC 20
#define CHC 16
#define HORC 12
#define NLC 8
#define EPSC 0.3f
#define RFC 13

// -------------------- device scratch (static, no allocation) --------------------
__device__ float g_XA[VV*BB*CHC*13];
__device__ float g_XB[VV*BB*CHC*13];
__device__ float g_XG[VV*BB*CHC*13];
__device__ float g_P [VV*BB*CHC*13];
__device__ float g_Q [VV*BB*CHC*13];
__device__ float g_skip[VV*BB*CHC];
__device__ float g_real[BB*VV*DGC];
__device__ float g_img [BB*VV*DGC];
__device__ float g_feat[BB*VV*60];
__device__ float g_adj [VV*VV];
__device__ float g_adjT[VV*VV];
__device__ float g_A2  [VV*VV];
__device__ float g_part[4*VV*VV];
__device__ float g_ct[VV], g_st[VV];
__device__ float g_Cw[DGC*24], g_Sw[DGC*24];
__device__ float g_wc[VV*60], g_bc[VV];
__device__ float g_WX[NLC*CHC*CHC], g_WP[NLC*CHC*CHC], g_WQ[NLC*CHC*CHC];
__device__ float g_bnsc[NLC*CHC], g_bnsh[NLC*CHC];

__device__ __forceinline__ float sigm(float x) { return 1.f / (1.f + expf(-x)); }

// -------------------- setup: fold constants --------------------
__global__ void setup_kernel(const float* __restrict__ lin_W,
                             const float* __restrict__ fc1_W, const float* __restrict__ fc1_b,
                             const float* __restrict__ fc2_W, const float* __restrict__ fc2_b,
                             const float* __restrict__ fc3_W, const float* __restrict__ fc3_b,
                             const float* __restrict__ gconv_W,
                             const float* __restrict__ bn_gamma, const float* __restrict__ bn_beta,
                             const float* __restrict__ bn_mean, const float* __restrict__ bn_var) {
    int idx0 = blockIdx.x * blockDim.x + threadIdx.x;
    int stride = gridDim.x * blockDim.x;
    const double PI = 3.14159265358979323846;
    for (int i = idx0; i < 512; i += stride) {
        double a = 2.0 * PI * (double)i / 512.0;
        g_ct[i] = (float)cos(a); g_st[i] = (float)sin(a);
    }
    for (int i = idx0; i < DGC*24; i += stride) {
        int d = i / 24, n = i % 24;
        float cs = 0.f, sn = 0.f;
        for (int j = 0; j < 24; j++) {
            double a = 2.0 * PI * (double)((j*n) % 24) / 24.0;
            cs += lin_W[d*24+j] * (float)cos(a);
            sn += lin_W[d*24+j] * (float)(-sin(a));
        }
        g_Cw[i] = cs; g_Sw[i] = sn;
    }
    for (int i = idx0; i < VV*60; i += stride) {
        int w = i / 60, j = i % 60;
        float v = (j < 20) ? fc1_W[w*20+j] : (j < 40) ? fc2_W[w*20+j-20] : fc3_W[w*20+j-40];
        g_wc[i] = v;
    }
    for (int i = idx0; i < VV; i += stride) g_bc[i] = fc1_b[i] + fc2_b[i] + fc3_b[i];
    for (int i = idx0; i < NLC*256; i += stride) {
        int L = i >> 8, ci = i & 15, co = (i >> 4) & 15;
        const float* G = gconv_W + (size_t)(L*16 + co)*64;
        float w1 = G[ci], w2 = G[16+ci], w3 = G[32+ci], w4 = G[48+ci];
        g_WX[i] = EPSC*(w1+w3) + EPSC*EPSC*(w2+w4);
        g_WP[i] = (w1 - w3) + 2.f*EPSC*(w2 - w4);
        g_WQ[i] = w2 + w4;
    }
    for (int i = idx0; i < NLC*CHC; i += stride) {
        float sc = bn_gamma[i] / sqrtf(bn_var[i] + 1e-5f);
        g_bnsc[i] = sc;
        g_bnsh[i] = bn_beta[i] - bn_mean[i]*sc;
    }
}

// -------------------- DFT(24) folded into linear layer + Am/S features --------------------
__global__ void fftlin_kernel(const float* __restrict__ input, const float* __restrict__ lin_b) {
    int bv = blockIdx.x; int b = bv >> 9, v = bv & 511;
    __shared__ float xr[24];
    int tid = threadIdx.x;
    if (tid < 24) {
        int t = tid >> 1, f = tid & 1;
        xr[tid] = input[(((size_t)t*BB + b)*VV + v)*FINC + f];
    }
    __syncthreads();
    if (tid < DGC) {
        float re = lin_b[tid], im = lin_b[tid];
        #pragma unroll
        for (int n = 0; n < 24; n++) {
            re += xr[n] * g_Cw[tid*24+n];
            im += xr[n] * g_Sw[tid*24+n];
        }
        int base = (b*VV + v)*DGC + tid;
        g_real[base] = re; g_img[base] = im;
        int fb = (b*VV + v)*60 + tid;
        g_feat[fb + 20] = sqrtf(re*re + im*im);
        g_feat[fb + 40] = atanf(re / (im + 1e-4f));
    }
}

// -------------------- irfft over the V axis (n=512, crop to 257 coeffs) --------------------
__global__ void irfft_kernel() {
    __shared__ float ct[512], st[512];
    __shared__ float partial[160];
    int bm = blockIdx.x; int b = bm >> 9, m = bm & 511;
    int tid = threadIdx.x;  // 160
    for (int i = tid; i < 512; i += 160) { ct[i] = g_ct[i]; st[i] = g_st[i]; }
    __syncthreads();
    int d = tid % 20, kg = tid / 20;  // kg 0..7
    const float* R = g_real + (size_t)b * VV * DGC;
    const float* I = g_img  + (size_t)b * VV * DGC;
    float s = 0.f;
    for (int k = 1 + kg; k <= 255; k += 8) {
        int a = (k * m) & 511;
        s += R[k*20 + d] * ct[a] - I[k*20 + d] * st[a];
    }
    s *= 2.f;
    if (kg == 0) {
        s += R[d];
        s += ((m & 1) ? -1.f : 1.f) * R[256*20 + d];
    }
    partial[tid] = s;
    __syncthreads();
    if (tid < 20) {
        float tot = 0.f;
        #pragma unroll
        for (int g = 0; g < 8; g++) tot += partial[g*20 + tid];
        g_feat[((size_t)b*VV + m)*60 + tid] = tot * (1.f/512.f);
    }
}

// -------------------- adj partial sums: 4 batch groups for grid parallelism --------------------
__global__ __launch_bounds__(256) void adj_part_kernel() {
    __shared__ float Ws[64][61];
    __shared__ float Fs[32][61];
    __shared__ float bcs[64];
    int bw = blockIdx.x * 64, bv = blockIdx.y * 32, bg = blockIdx.z;
    int tid = threadIdx.x;
    for (int idx = tid; idx < 64*60; idx += 256)
        Ws[idx/60][idx%60] = g_wc[(bw + idx/60)*60 + idx%60];
    if (tid < 64) bcs[tid] = g_bc[bw + tid];
    float acc[8] = {0,0,0,0,0,0,0,0};
    int w = tid & 63, vg = tid >> 6;  // vg 0..3
    for (int b = bg*8; b < bg*8 + 8; b++) {
        __syncthreads();
        for (int idx = tid; idx < 32*60; idx += 256)
            Fs[idx/60][idx%60] = g_feat[((size_t)b*VV + bv + idx/60)*60 + idx%60];
        __syncthreads();
        #pragma unroll
        for (int s = 0; s < 8; s++) {
            int vi = vg + 4*s;
            float d = bcs[w];
            #pragma unroll
            for (int j = 0; j < 60; j++) d += Fs[vi][j] * Ws[w][j];
            acc[s] += sigm(d * (1.f/3.f));
        }
    }
    #pragma unroll
    for (int s = 0; s < 8; s++)
        g_part[(size_t)bg*VV*VV + (size_t)(bv + vg + 4*s)*VV + bw + w] = acc[s];
}

__global__ void adj_final_kernel() {
    int i = blockIdx.x * 256 + threadIdx.x;  // 1024 blocks cover 262144
    float s = g_part[i] + g_part[VV*VV + i] + g_part[2*VV*VV + i] + g_part[3*VV*VV + i];
    g_adj[i] = sigm(s * (1.f/BB));
}

// -------------------- adj transpose (for A2 = adj @ adj via TN gemm) --------------------
__global__ void transpose_kernel() {
    __shared__ float t[32][33];
    int bx = blockIdx.x*32, by = blockIdx.y*32;
    int x = threadIdx.x, y = threadIdx.y;  // 32 x 8
    #pragma unroll
    for (int i = 0; i < 32; i += 8) t[y+i][x] = g_adj[(size_t)(by+y+i)*VV + bx + x];
    __syncthreads();
    #pragma unroll
    for (int i = 0; i < 32; i += 8) g_adjT[(size_t)(bx+y+i)*VV + by + x] = t[x][y+i];
}

// -------------------- FFMA2 GEMM tile: C[m,n] = sum_k A[k][m] * B[k][n], K=512 --------------------
__device__ __forceinline__ void gemm_tile_f2(const float* __restrict__ A, const float* __restrict__ Bm,
                                             float* __restrict__ C, int N, int bm, int bn) {
    __shared__ float AsD[8][256];   // A values duplicated into f32x2 pairs
    __shared__ float Bs[8][128];
    int tid = threadIdx.x;
    int tm = (tid >> 4) * 8;   // 0..120
    int tn = (tid & 15) * 8;   // 0..120
    int lr = tid >> 5;         // 0..7
    int lc = (tid & 31) * 4;   // 0..124
    unsigned long long acc[8][4];
    #pragma unroll
    for (int i = 0; i < 8; i++)
        #pragma unroll
        for (int j = 0; j < 4; j++) acc[i][j] = 0ull;
    float4 pa = *(const float4*)&A [(size_t)lr*VV + bm + lc];
    float4 pb = *(const float4*)&Bm[(size_t)lr*N  + bn + lc];
    for (int k0 = 0; k0 < 512; k0 += 8) {
        AsD[lr][2*lc+0] = pa.x; AsD[lr][2*lc+1] = pa.x;
        AsD[lr][2*lc+2] = pa.y; AsD[lr][2*lc+3] = pa.y;
        AsD[lr][2*lc+4] = pa.z; AsD[lr][2*lc+5] = pa.z;
        AsD[lr][2*lc+6] = pa.w; AsD[lr][2*lc+7] = pa.w;
        *(float4*)&Bs[lr][lc] = pb;
        __syncthreads();
        if (k0 + 8 < 512) {
            pa = *(const float4*)&A [(size_t)(k0+8+lr)*VV + bm + lc];
            pb = *(const float4*)&Bm[(size_t)(k0+8+lr)*N  + bn + lc];
        }
        #pragma unroll
        for (int kk = 0; kk < 8; kk++) {
            unsigned long long av[8], xv[4];
            const unsigned long long* ap = (const unsigned long long*)&AsD[kk][2*tm];
            const unsigned long long* xp = (const unsigned long long*)&Bs[kk][tn];
            #pragma unroll
            for (int i = 0; i < 8; i++) av[i] = ap[i];
            #pragma unroll
            for (int j = 0; j < 4; j++) xv[j] = xp[j];
            #pragma unroll
            for (int i = 0; i < 8; i++)
                #pragma unroll
                for (int j = 0; j < 4; j++)
                    asm("fma.rn.f32x2 %0, %1, %2, %0;" : "+l"(acc[i][j]) : "l"(av[i]), "l"(xv[j]));
        }
        __syncthreads();
    }
    #pragma unroll
    for (int i = 0; i < 8; i++) {
        unsigned long long* cp = (unsigned long long*)&C[(size_t)(bm + tm + i)*N + bn + tn];
        #pragma unroll
        for (int j = 0; j < 4; j++) cp[j] = acc[i][j];
    }
}

// Stacked per-layer diffusion: y<4 -> P = adj^T X, y>=4 -> Q = (adj@adj)^T-applied X
__global__ __launch_bounds__(256) void gemm_layer(int N) {
    int by = blockIdx.y;
    const float* A = (by < 4) ? g_adj : g_A2;
    float* C = (by < 4) ? g_P : g_Q;
    gemm_tile_f2(A, g_XG, C, N, (by & 3) * 128, blockIdx.x * 128);
}

// A2 = adj @ adj  (rows k, cols m):  A2[k][m] = sum_j adjT[j][k] * adj[j][m]
__global__ __launch_bounds__(256) void gemm_a2() {
    gemm_tile_f2(g_adjT, g_adj, g_A2, VV, blockIdx.y * 128, blockIdx.x * 128);
}

// -------------------- start 1x1 conv + gate layer 0 + skip init --------------------
__global__ void start_gate_kernel(const float* __restrict__ input,
                                  const float* __restrict__ start_W, const float* __restrict__ start_b,
                                  const float* __restrict__ filt_W, const float* __restrict__ filt_b,
                                  const float* __restrict__ gate_W, const float* __restrict__ gate_b,
                                  const float* __restrict__ skip_W, const float* __restrict__ skip_b) {
    int vb = blockIdx.x; int v = vb >> 5, b = vb & 31;
    __shared__ float xin[FINC][13];
    __shared__ float xn[CHC][13];
    __shared__ float xg[CHC][12];
    __shared__ float fw[512], gw[512], sw[256];
    int c = threadIdx.x, l = threadIdx.y;
    int tid = l*16 + c;
    for (int idx = tid; idx < 512; idx += 208) { fw[idx] = filt_W[idx]; gw[idx] = gate_W[idx]; }
    for (int idx = tid; idx < 256; idx += 208) sw[idx] = skip_W[idx];
    if (tid < FINC*13) {
        int f = tid / 13, ll = tid % 13;
        xin[f][ll] = (ll == 0) ? 0.f : input[((((size_t)(ll-1))*BB + b)*VV + v)*FINC + f];
    }
    __syncthreads();
    float val = start_b[c] + start_W[c*2+0]*xin[0][l] + start_W[c*2+1]*xin[1][l];
    xn[c][l] = val;
    g_XA[(((size_t)v*BB + b)*CHC + c)*13 + l] = val;
    __syncthreads();
    if (l < 12) {
        float f = filt_b[c], g = gate_b[c];
        #pragma unroll
        for (int ci = 0; ci < CHC; ci++) {
            float x0 = xn[ci][l], x1 = xn[ci][l+1];
            f += fw[(c*16+ci)*2]*x0 + fw[(c*16+ci)*2+1]*x1;
            g += gw[(c*16+ci)*2]*x0 + gw[(c*16+ci)*2+1]*x1;
        }
        float vv = tanhf(f) * sigm(g);
        xg[c][l] = vv;
        g_XG[((size_t)(v*BB + b)*CHC + c)*12 + l] = vv;
    }
    __syncthreads();
    if (l == 11) {
        float s = skip_b[c];
        #pragma unroll
        for (int ci = 0; ci < CHC; ci++) s += sw[c*16+ci] * xg[ci][11];
        g_skip[((size_t)v*BB + b)*CHC + c] = s;
    }
}

// -------------------- fused: combine(layer) + gate(layer+1) + skip --------------------
__global__ void comb_gate_kernel(int layer, int Lin, int Lout, int dil, int flip,
                                 int nLout, int ndil,
                                 const float* __restrict__ gconv_b,
                                 const float* __restrict__ filt_W, const float* __restrict__ filt_b,
                                 const float* __restrict__ gate_W, const float* __restrict__ gate_b,
                                 const float* __restrict__ skip_W, const float* __restrict__ skip_b) {
    int nlayer = layer + 1;
    const float* Xres = flip ? g_XB : g_XA;
    float* Xout = flip ? g_XA : g_XB;
    int vb = blockIdx.x; int v = vb >> 5, b = vb & 31;
    __shared__ float xg[CHC][12], pp[CHC][12], qq[CHC][12], xn[CHC][12];
    __shared__ float wx[256], wp[256], wq[256];
    __shared__ float fw[512], gw[512], sw[256];
    int c = threadIdx.x, l = threadIdx.y;
    int tid = l*16 + c;
    for (int idx = tid; idx < 256; idx += 208) {
        wx[idx] = g_WX[layer*256+idx];
        wp[idx] = g_WP[layer*256+idx];
        wq[idx] = g_WQ[layer*256+idx];
        sw[idx] = skip_W[nlayer*256+idx];
    }
    for (int idx = tid; idx < 512; idx += 208) {
        fw[idx] = filt_W[nlayer*512+idx];
        gw[idx] = gate_W[nlayer*512+idx];
    }
    size_t base = ((size_t)(v*BB + b)*CHC + c)*Lout;
    if (l < Lout) {
        xg[c][l] = g_XG[base + l];
        pp[c][l] = g_P[base + l];
        qq[c][l] = g_Q[base + l];
    }
    __syncthreads();
    if (l < Lout) {
        float h = gconv_b[layer*16+c];
        #pragma unroll
        for (int ci = 0; ci < CHC; ci++)
            h += wx[c*16+ci]*xg[ci][l] + wp[c*16+ci]*pp[ci][l] + wq[c*16+ci]*qq[ci][l];
        float t = h + Xres[((size_t)(v*BB + b)*CHC + c)*Lin + l + dil];
        float xv = t * g_bnsc[layer*16+c] + g_bnsh[layer*16+c];
        xn[c][l] = xv;
        if (layer < 6) Xout[base + l] = xv;   // residual needed by next combine only
    }
    __syncthreads();
    if (l < nLout) {
        float f = filt_b[nlayer*16+c], g = gate_b[nlayer*16+c];
        #pragma unroll
        for (int ci = 0; ci < CHC; ci++) {
            float x0 = xn[ci][l], x1 = xn[ci][l+ndil];
            f += fw[(c*16+ci)*2]*x0 + fw[(c*16+ci)*2+1]*x1;
            g += gw[(c*16+ci)*2]*x0 + gw[(c*16+ci)*2+1]*x1;
        }
        float vv = tanhf(f) * sigm(g);
        qq[c][l] = vv;   // reuse qq as gate output
        g_XG[((size_t)(v*BB + b)*CHC + c)*nLout + l] = vv;
    }
    __syncthreads();
    if (l == nLout - 1) {
        float s = skip_b[nlayer*16+c];
        #pragma unroll
        for (int ci = 0; ci < CHC; ci++) s += sw[c*16+ci] * qq[ci][nLout-1];
        g_skip[((size_t)v*BB + b)*CHC + c] += s;
    }
}

// -------------------- end head --------------------
__global__ void end_kernel(const float* __restrict__ end1_W, const float* __restrict__ end1_b,
                           const float* __restrict__ end2_W, const float* __restrict__ end2_b,
                           float* __restrict__ out) {
    int vb = blockIdx.x; int v = vb >> 5, b = vb & 31;
    __shared__ float o1[16], o2[16];
    int t = threadIdx.x;  // 16
    o1[t] = fmaxf(g_skip[((size_t)v*BB + b)*CHC + t], 0.f);
    __syncthreads();
    float a = end1_b[t];
    #pragma unroll
    for (int ci = 0; ci < 16; ci++) a += end1_W[t*16+ci] * o1[ci];
    o2[t] = fmaxf(a, 0.f);
    __syncthreads();
    if (t < HORC) {
        float r = end2_b[t];
        #pragma unroll
        for (int c = 0; c < 16; c++) r += end2_W[t*16+c] * o2[c];
        out[((size_t)b*HORC + t)*VV + v] = r;
    }
}

__global__ void adjcopy_kernel(float* __restrict__ out) {
    int i = blockIdx.x * 256 + threadIdx.x;
    if (i < VV*VV) out[i] = g_adj[i];
}

// -------------------- launch --------------------
extern "C" void kernel_launch(void* const* d_in, const int* in_sizes, int n_in,
                              void* d_out, int out_size) {
    const float* input    = (const float*)d_in[0];
    const float* start_W  = (const float*)d_in[1];
    const float* start_b  = (const float*)d_in[2];
    const float* filt_W   = (const float*)d_in[3];
    const float* filt_b   = (const float*)d_in[4];
    const float* gate_W   = (const float*)d_in[5];
    const float* gate_b   = (const float*)d_in[6];
    const float* skip_W   = (const float*)d_in[7];
    const float* skip_b   = (const float*)d_in[8];
    const float* gconv_W  = (const float*)d_in[9];
    const float* gconv_b  = (const float*)d_in[10];
    const float* bn_gamma = (const float*)d_in[11];
    const float* bn_beta  = (const float*)d_in[12];
    const float* bn_mean  = (const float*)d_in[13];
    const float* bn_var   = (const float*)d_in[14];
    const float* end1_W   = (const float*)d_in[15];
    const float* end1_b   = (const float*)d_in[16];
    const float* end2_W   = (const float*)d_in[17];
    const float* end2_b   = (const float*)d_in[18];
    const float* lin_W    = (const float*)d_in[19];
    const float* lin_b    = (const float*)d_in[20];
    const float* fc1_W    = (const float*)d_in[21];
    const float* fc1_b    = (const float*)d_in[22];
    const float* fc2_W    = (const float*)d_in[23];
    const float* fc2_b    = (const float*)d_in[24];
    const float* fc3_W    = (const float*)d_in[25];
    const float* fc3_b    = (const float*)d_in[26];
    float* out = (float*)d_out;

    setup_kernel<<<64, 256>>>(lin_W, fc1_W, fc1_b, fc2_W, fc2_b, fc3_W, fc3_b,
                              gconv_W, bn_gamma, bn_beta, bn_mean, bn_var);
    fftlin_kernel<<<BB*VV, 32>>>(input, lin_b);
    irfft_kernel<<<BB*VV, 160>>>();
    adj_part_kernel<<<dim3(VV/64, VV/32, 4), 256>>>();
    adj_final_kernel<<<VV*VV/256, 256>>>();
    transpose_kernel<<<dim3(16, 16), dim3(32, 8)>>>();
    gemm_a2<<<dim3(4, 4), 256>>>();
    start_gate_kernel<<<VV*BB, dim3(16, 13)>>>(input, start_W, start_b,
                                               filt_W, filt_b, gate_W, gate_b, skip_W, skip_b);

    static const int dils[NLC] = {1, 2, 1, 2, 1, 2, 1, 2};
    int L = 13;   // length of residual x_i
    int Lo = 12;  // gate output length of layer i
    for (int i = 0; i < 7; i++) {
        int N = BB * CHC * Lo;  // 512 * Lo
        gemm_layer<<<dim3(N/128, 8), 256>>>(N);
        int nLo = Lo - dils[i+1];
        comb_gate_kernel<<<VV*BB, dim3(16, 13)>>>(i, L, Lo, dils[i], i & 1, nLo, dils[i+1],
                                                  gconv_b, filt_W, filt_b, gate_W, gate_b,
                                                  skip_W, skip_b);
        L = Lo; Lo = nLo;
    }
    end_kernel<<<VV*BB, 16>>>(end1_W, end1_b, end2_W, end2_b, out);
    if (out_size >= BB*HORC*VV + VV*VV)
        adjcopy_kernel<<<(VV*VV + 255)/256, 256>>>(out + BB*HORC*VV);
}

// round 12
// speedup vs baseline: 1.5856x; 1.4980x over previous
#include <cuda_runtime.h>
#include <math.h>

#define BB  32
#define VV  512
#define TT  12
#define FINC 2
#define DGC 20
#define CHC 16
#define HORC 12
#define NLC 8
#define EPSC 0.3f
#define RFC 13

// -------------------- device scratch (static, no allocation) --------------------
__device__ float g_XA[VV*BB*CHC*13];
__device__ float g_XB[VV*BB*CHC*13];
__device__ float g_XG[VV*BB*CHC*13];
__device__ float g_P [VV*BB*CHC*13];
__device__ float g_Q [VV*BB*CHC*13];
__device__ float g_skip[VV*BB*CHC];
__device__ float g_real[BB*VV*DGC];
__device__ float g_img [BB*VV*DGC];
__device__ float g_feat[BB*VV*60];
__device__ float g_adj [VV*VV];
__device__ float g_adjT[VV*VV];
__device__ float g_A2  [VV*VV];
__device__ float g_part[4*VV*VV];
__device__ float g_Tct[257*VV], g_Tst[257*VV];
__device__ float g_ct[VV], g_st[VV];
__device__ float g_Cw[DGC*24], g_Sw[DGC*24];
__device__ float g_wc[VV*60], g_bc[VV];
__device__ float g_WX[NLC*CHC*CHC], g_WP[NLC*CHC*CHC], g_WQ[NLC*CHC*CHC];
__device__ float g_bnsc[NLC*CHC], g_bnsh[NLC*CHC];

__device__ __forceinline__ float sigm(float x) { return 1.f / (1.f + expf(-x)); }

// -------------------- setup: fold constants --------------------
__global__ void setup_kernel(const float* __restrict__ lin_W,
                             const float* __restrict__ fc1_W, const float* __restrict__ fc1_b,
                             const float* __restrict__ fc2_W, const float* __restrict__ fc2_b,
                             const float* __restrict__ fc3_W, const float* __restrict__ fc3_b,
                             const float* __restrict__ gconv_W,
                             const float* __restrict__ bn_gamma, const float* __restrict__ bn_beta,
                             const float* __restrict__ bn_mean, const float* __restrict__ bn_var) {
    int idx0 = blockIdx.x * blockDim.x + threadIdx.x;
    int stride = gridDim.x * blockDim.x;
    const double PI = 3.14159265358979323846;
    for (int i = idx0; i < 512; i += stride) {
        double a = 2.0 * PI * (double)i / 512.0;
        g_ct[i] = (float)cos(a); g_st[i] = (float)sin(a);
    }
    for (int i = idx0; i < DGC*24; i += stride) {
        int d = i / 24, n = i % 24;
        float cs = 0.f, sn = 0.f;
        for (int j = 0; j < 24; j++) {
            double a = 2.0 * PI * (double)((j*n) % 24) / 24.0;
            cs += lin_W[d*24+j] * (float)cos(a);
            sn += lin_W[d*24+j] * (float)(-sin(a));
        }
        g_Cw[i] = cs; g_Sw[i] = sn;
    }
    for (int i = idx0; i < VV*60; i += stride) {
        int w = i / 60, j = i % 60;
        float v = (j < 20) ? fc1_W[w*20+j] : (j < 40) ? fc2_W[w*20+j-20] : fc3_W[w*20+j-40];
        g_wc[i] = v;
    }
    for (int i = idx0; i < VV; i += stride) g_bc[i] = fc1_b[i] + fc2_b[i] + fc3_b[i];
    for (int i = idx0; i < NLC*256; i += stride) {
        int L = i >> 8, ci = i & 15, co = (i >> 4) & 15;
        const float* G = gconv_W + (size_t)(L*16 + co)*64;
        float w1 = G[ci], w2 = G[16+ci], w3 = G[32+ci], w4 = G[48+ci];
        g_WX[i] = EPSC*(w1+w3) + EPSC*EPSC*(w2+w4);
        g_WP[i] = (w1 - w3) + 2.f*EPSC*(w2 - w4);
        g_WQ[i] = w2 + w4;
    }
    for (int i = idx0; i < NLC*CHC; i += stride) {
        float sc = bn_gamma[i] / sqrtf(bn_var[i] + 1e-5f);
        g_bnsc[i] = sc;
        g_bnsh[i] = bn_beta[i] - bn_mean[i]*sc;
    }
}

// -------------------- irfft trig table: Tct[k][m] = w_k*cos(2pi km/512)/512 --------------------
__global__ void trig_kernel() {
    int i = blockIdx.x * 256 + threadIdx.x;
    if (i < 257*512) {
        int k = i >> 9, m = i & 511;
        float w = (k == 0 || k == 256) ? (1.f/512.f) : (2.f/512.f);
        int a = (k * m) & 511;
        g_Tct[i] = w * g_ct[a];
        g_Tst[i] = w * g_st[a];
    }
}

// -------------------- DFT(24) folded into linear layer, 128 pairs/block --------------------
__global__ __launch_bounds__(256) void fftlin_kernel(const float* __restrict__ input,
                                                     const float* __restrict__ lin_b) {
    __shared__ float xr[128*25];
    __shared__ float sCw[480], sSw[480], sb[20];
    int tid = threadIdx.x;
    int p0 = blockIdx.x * 128;           // pair index = b*512 + v
    int b = p0 >> 9, v0 = p0 & 511;
    for (int i = tid; i < 480; i += 256) { sCw[i] = g_Cw[i]; sSw[i] = g_Sw[i]; }
    if (tid < 20) sb[tid] = lin_b[tid];
    {
        int f = tid & 1, pl = tid >> 1;
        #pragma unroll
        for (int tt = 0; tt < 12; tt++) {
            float val = input[((size_t)(tt*32 + b)*512 + v0)*2 + tid];
            xr[pl*25 + tt*2 + f] = val;
        }
    }
    __syncthreads();
    int ml = tid & 127, dh = tid >> 7, d0 = dh * 10;
    float re[10], im[10];
    #pragma unroll
    for (int i = 0; i < 10; i++) { re[i] = sb[d0+i]; im[i] = sb[d0+i]; }
    #pragma unroll
    for (int n = 0; n < 24; n++) {
        float x = xr[ml*25 + n];
        #pragma unroll
        for (int i = 0; i < 10; i++) {
            re[i] += x * sCw[(d0+i)*24 + n];
            im[i] += x * sSw[(d0+i)*24 + n];
        }
    }
    size_t base = (size_t)(p0 + ml) * 20 + d0;
    size_t fb = (size_t)(p0 + ml) * 60 + d0;
    #pragma unroll
    for (int i = 0; i < 10; i++) {
        g_real[base + i] = re[i];
        g_img [base + i] = im[i];
        g_feat[fb + 20 + i] = sqrtf(re[i]*re[i] + im[i]*im[i]);
        g_feat[fb + 40 + i] = atanf(re[i] / (im[i] + 1e-4f));
    }
}

// -------------------- irfft as tiled GEMM vs trig table --------------------
__global__ __launch_bounds__(256) void irfft2_kernel() {
    __shared__ float Rs[32*20], Is[32*20];
    int b = blockIdx.y;
    int m0 = blockIdx.x * 128;
    int tid = threadIdx.x;
    int ml = tid & 127, dh = tid >> 7, d0 = dh * 10;
    const float* Rg = g_real + (size_t)b * 512 * 20;
    const float* Ig = g_img  + (size_t)b * 512 * 20;
    float acc[10];
    #pragma unroll
    for (int i = 0; i < 10; i++) acc[i] = 0.f;
    for (int k0 = 0; k0 < 257; k0 += 32) {
        __syncthreads();
        for (int i = tid; i < 640; i += 256) {
            int k = k0 + i / 20;
            Rs[i] = (k < 257) ? Rg[(size_t)k*20 + i%20] : 0.f;
            Is[i] = (k < 257) ? Ig[(size_t)k*20 + i%20] : 0.f;
        }
        __syncthreads();
        int kmax = min(32, 257 - k0);
        for (int kk = 0; kk < kmax; kk++) {
            float tc = g_Tct[(size_t)(k0+kk)*512 + m0 + ml];
            float ts = g_Tst[(size_t)(k0+kk)*512 + m0 + ml];
            #pragma unroll
            for (int i = 0; i < 10; i++)
                acc[i] += tc * Rs[kk*20 + d0 + i] - ts * Is[kk*20 + d0 + i];
        }
    }
    size_t fb = ((size_t)b*512 + m0 + ml) * 60 + d0;
    #pragma unroll
    for (int i = 0; i < 10; i++) g_feat[fb + i] = acc[i];
}

// -------------------- adj partial sums --------------------
__global__ __launch_bounds__(256) void adj_part_kernel() {
    __shared__ float Ws[64][61];
    __shared__ float Fs[32][61];
    __shared__ float bcs[64];
    int bw = blockIdx.x * 64, bv = blockIdx.y * 32, bg = blockIdx.z;
    int tid = threadIdx.x;
    for (int idx = tid; idx < 64*60; idx += 256)
        Ws[idx/60][idx%60] = g_wc[(bw + idx/60)*60 + idx%60];
    if (tid < 64) bcs[tid] = g_bc[bw + tid];
    float acc[8] = {0,0,0,0,0,0,0,0};
    int w = tid & 63, vg = tid >> 6;
    for (int b = bg*8; b < bg*8 + 8; b++) {
        __syncthreads();
        for (int idx = tid; idx < 32*60; idx += 256)
            Fs[idx/60][idx%60] = g_feat[((size_t)b*VV + bv + idx/60)*60 + idx%60];
        __syncthreads();
        #pragma unroll
        for (int s = 0; s < 8; s++) {
            int vi = vg + 4*s;
            float d = bcs[w];
            #pragma unroll
            for (int j = 0; j < 60; j++) d += Fs[vi][j] * Ws[w][j];
            acc[s] += sigm(d * (1.f/3.f));
        }
    }
    #pragma unroll
    for (int s = 0; s < 8; s++)
        g_part[(size_t)bg*VV*VV + (size_t)(bv + vg + 4*s)*VV + bw + w] = acc[s];
}

__global__ void adj_final_kernel() {
    int i = blockIdx.x * 256 + threadIdx.x;
    float s = g_part[i] + g_part[VV*VV + i] + g_part[2*VV*VV + i] + g_part[3*VV*VV + i];
    g_adj[i] = sigm(s * (1.f/BB));
}

__global__ void transpose_kernel() {
    __shared__ float t[32][33];
    int bx = blockIdx.x*32, by = blockIdx.y*32;
    int x = threadIdx.x, y = threadIdx.y;
    #pragma unroll
    for (int i = 0; i < 32; i += 8) t[y+i][x] = g_adj[(size_t)(by+y+i)*VV + bx + x];
    __syncthreads();
    #pragma unroll
    for (int i = 0; i < 32; i += 8) g_adjT[(size_t)(bx+y+i)*VV + by + x] = t[x][y+i];
}

// -------------------- FFMA2 GEMM tile --------------------
__device__ __forceinline__ void gemm_tile_f2(const float* __restrict__ A, const float* __restrict__ Bm,
                                             float* __restrict__ C, int N, int bm, int bn) {
    __shared__ float AsD[8][256];
    __shared__ float Bs[8][128];
    int tid = threadIdx.x;
    int tm = (tid >> 4) * 8;
    int tn = (tid & 15) * 8;
    int lr = tid >> 5;
    int lc = (tid & 31) * 4;
    unsigned long long acc[8][4];
    #pragma unroll
    for (int i = 0; i < 8; i++)
        #pragma unroll
        for (int j = 0; j < 4; j++) acc[i][j] = 0ull;
    float4 pa = *(const float4*)&A [(size_t)lr*VV + bm + lc];
    float4 pb = *(const float4*)&Bm[(size_t)lr*N  + bn + lc];
    for (int k0 = 0; k0 < 512; k0 += 8) {
        AsD[lr][2*lc+0] = pa.x; AsD[lr][2*lc+1] = pa.x;
        AsD[lr][2*lc+2] = pa.y; AsD[lr][2*lc+3] = pa.y;
        AsD[lr][2*lc+4] = pa.z; AsD[lr][2*lc+5] = pa.z;
        AsD[lr][2*lc+6] = pa.w; AsD[lr][2*lc+7] = pa.w;
        *(float4*)&Bs[lr][lc] = pb;
        __syncthreads();
        if (k0 + 8 < 512) {
            pa = *(const float4*)&A [(size_t)(k0+8+lr)*VV + bm + lc];
            pb = *(const float4*)&Bm[(size_t)(k0+8+lr)*N  + bn + lc];
        }
        #pragma unroll
        for (int kk = 0; kk < 8; kk++) {
            unsigned long long av[8], xv[4];
            const unsigned long long* ap = (const unsigned long long*)&AsD[kk][2*tm];
            const unsigned long long* xp = (const unsigned long long*)&Bs[kk][tn];
            #pragma unroll
            for (int i = 0; i < 8; i++) av[i] = ap[i];
            #pragma unroll
            for (int j = 0; j < 4; j++) xv[j] = xp[j];
            #pragma unroll
            for (int i = 0; i < 8; i++)
                #pragma unroll
                for (int j = 0; j < 4; j++)
                    asm("fma.rn.f32x2 %0, %1, %2, %0;" : "+l"(acc[i][j]) : "l"(av[i]), "l"(xv[j]));
        }
        __syncthreads();
    }
    #pragma unroll
    for (int i = 0; i < 8; i++) {
        unsigned long long* cp = (unsigned long long*)&C[(size_t)(bm + tm + i)*N + bn + tn];
        #pragma unroll
        for (int j = 0; j < 4; j++) cp[j] = acc[i][j];
    }
}

__global__ __launch_bounds__(256) void gemm_layer(int N) {
    int by = blockIdx.y;
    const float* A = (by < 4) ? g_adj : g_A2;
    float* C = (by < 4) ? g_P : g_Q;
    gemm_tile_f2(A, g_XG, C, N, (by & 3) * 128, blockIdx.x * 128);
}

__global__ __launch_bounds__(256) void gemm_a2() {
    gemm_tile_f2(g_adjT, g_adj, g_A2, VV, blockIdx.y * 128, blockIdx.x * 128);
}

// -------------------- start conv + gate(0) + skip init : 8 pairs/block --------------------
__global__ __launch_bounds__(256) void start_gate_kernel(const float* __restrict__ input,
        const float* __restrict__ start_W, const float* __restrict__ start_b,
        const float* __restrict__ filt_W, const float* __restrict__ filt_b,
        const float* __restrict__ gate_W, const float* __restrict__ gate_b,
        const float* __restrict__ skip_W, const float* __restrict__ skip_b) {
    __shared__ float xin[8*2*13];
    __shared__ float s_xn[8*16*13];
    __shared__ float fw0T[256], fw1T[256], gw0T[256], gw1T[256], swT[256];
    __shared__ float sW[32], sB[16], fb[16], gb[16], sb2[16];
    int tid = threadIdx.x;
    int vb0 = blockIdx.x * 8;
    for (int i = tid; i < 256; i += 256) {
        int c = i & 15, ci = i >> 4;
        fw0T[i] = filt_W[(c*16+ci)*2];
        fw1T[i] = filt_W[(c*16+ci)*2+1];
        gw0T[i] = gate_W[(c*16+ci)*2];
        gw1T[i] = gate_W[(c*16+ci)*2+1];
        swT[i]  = skip_W[c*16+ci];
    }
    if (tid < 32) sW[tid] = start_W[tid];
    if (tid < 16) { sB[tid] = start_b[tid]; fb[tid] = filt_b[tid]; gb[tid] = gate_b[tid]; sb2[tid] = skip_b[tid]; }
    for (int i = tid; i < 8*2*13; i += 256) {
        int l = i % 13, pf = i / 13, f = pf & 1, p = pf >> 1;
        int vb = vb0 + p; int v = vb >> 5, b = vb & 31;
        xin[i] = (l == 0) ? 0.f : input[((((size_t)(l-1))*32 + b)*512 + v)*2 + f];
    }
    __syncthreads();
    for (int i = tid; i < 8*16*13; i += 256) {
        int l = i % 13, pc = i / 13, c = pc & 15, p = pc >> 4;
        float val = sB[c] + sW[c*2]*xin[(p*2)*13 + l] + sW[c*2+1]*xin[(p*2+1)*13 + l];
        s_xn[pc*13 + l] = val;
        g_XA[(size_t)(vb0 + p)*16*13 + c*13 + l] = val;
    }
    __syncthreads();
    for (int i = tid; i < 8*16*12; i += 256) {
        int l = i % 12, pc = i / 12, c = pc & 15, p = pc >> 4;
        float f = fb[c], g = gb[c];
        #pragma unroll
        for (int ci = 0; ci < 16; ci++) {
            float x0 = s_xn[(p*16+ci)*13 + l], x1 = s_xn[(p*16+ci)*13 + l + 1];
            f += fw0T[ci*16+c]*x0 + fw1T[ci*16+c]*x1;
            g += gw0T[ci*16+c]*x0 + gw1T[ci*16+c]*x1;
        }
        float vv = tanhf(f) * sigm(g);
        xin[0] = xin[0];  // no-op
        s_xn[pc*13 + l] = s_xn[pc*13 + l];  // keep xn intact (vv stored below)
        g_XG[(size_t)(vb0 + p)*16*12 + c*12 + l] = vv;
        if (l == 11) {
            // stash gate tail for skip via xin reuse (8*16 = 128 <= 208 slots)
            xin[pc] = vv;
        }
    }
    __syncthreads();
    if (tid < 128) {
        int c = tid & 15, p = tid >> 4;
        float s = sb2[c];
        #pragma unroll
        for (int ci = 0; ci < 16; ci++) s += swT[ci*16+c] * xin[p*16+ci];
        g_skip[(size_t)(vb0 + p)*16 + c] = s;
    }
}

// -------------------- fused combine(layer) + gate(layer+1) + skip : 8 pairs/block --------------------
__global__ __launch_bounds__(256) void comb_gate_kernel(int layer, int Lin, int Lout, int dil,
        int flip, int nLout, int ndil,
        const float* __restrict__ gconv_b,
        const float* __restrict__ filt_W, const float* __restrict__ filt_b,
        const float* __restrict__ gate_W, const float* __restrict__ gate_b,
        const float* __restrict__ skip_W, const float* __restrict__ skip_b) {
    int nlayer = layer + 1;
    const float* Xres = flip ? g_XB : g_XA;
    float* Xout = flip ? g_XA : g_XB;
    __shared__ float s_xg[8*16*12], s_pp[8*16*12], s_qq[8*16*12], s_xn[8*16*12];
    __shared__ float wxT[256], wpT[256], wqT[256], swT[256];
    __shared__ float fw0T[256], fw1T[256], gw0T[256], gw1T[256];
    __shared__ float gcb[16], bnsc[16], bnsh[16], fb[16], gb[16], sb2[16];
    int tid = threadIdx.x;
    int vb0 = blockIdx.x * 8;
    for (int i = tid; i < 256; i += 256) {
        int c = i & 15, ci = i >> 4;
        wxT[i] = g_WX[layer*256 + c*16+ci];
        wpT[i] = g_WP[layer*256 + c*16+ci];
        wqT[i] = g_WQ[layer*256 + c*16+ci];
        swT[i] = skip_W[nlayer*256 + c*16+ci];
        fw0T[i] = filt_W[nlayer*512 + (c*16+ci)*2];
        fw1T[i] = filt_W[nlayer*512 + (c*16+ci)*2+1];
        gw0T[i] = gate_W[nlayer*512 + (c*16+ci)*2];
        gw1T[i] = gate_W[nlayer*512 + (c*16+ci)*2+1];
    }
    if (tid < 16) {
        gcb[tid]  = gconv_b[layer*16+tid];
        bnsc[tid] = g_bnsc[layer*16+tid];
        bnsh[tid] = g_bnsh[layer*16+tid];
        fb[tid]   = filt_b[nlayer*16+tid];
        gb[tid]   = gate_b[nlayer*16+tid];
        sb2[tid]  = skip_b[nlayer*16+tid];
    }
    {
        const float* srcX = g_XG + (size_t)vb0*16*Lout;
        const float* srcP = g_P  + (size_t)vb0*16*Lout;
        const float* srcQ = g_Q  + (size_t)vb0*16*Lout;
        int nload = 8*16*Lout;
        for (int i = tid; i < nload; i += 256) {
            int l = i % Lout, pc = i / Lout;
            s_xg[pc*12 + l] = srcX[i];
            s_pp[pc*12 + l] = srcP[i];
            s_qq[pc*12 + l] = srcQ[i];
        }
    }
    __syncthreads();
    for (int i = tid; i < 8*16*Lout; i += 256) {
        int l = i % Lout, pc = i / Lout, c = pc & 15, p = pc >> 4;
        float h = gcb[c];
        #pragma unroll
        for (int ci = 0; ci < 16; ci++) {
            int a = (p*16+ci)*12 + l;
            h += wxT[ci*16+c]*s_xg[a] + wpT[ci*16+c]*s_pp[a] + wqT[ci*16+c]*s_qq[a];
        }
        float res = Xres[(size_t)(vb0+p)*16*Lin + c*Lin + l + dil];
        float xv = (h + res) * bnsc[c] + bnsh[c];
        s_xn[pc*12 + l] = xv;
        if (layer < 6) Xout[(size_t)(vb0+p)*16*Lout + c*Lout + l] = xv;
    }
    __syncthreads();
    for (int i = tid; i < 8*16*nLout; i += 256) {
        int l = i % nLout, pc = i / nLout, c = pc & 15, p = pc >> 4;
        float f = fb[c], g = gb[c];
        #pragma unroll
        for (int ci = 0; ci < 16; ci++) {
            int a = (p*16+ci)*12 + l;
            float x0 = s_xn[a], x1 = s_xn[a + ndil];
            f += fw0T[ci*16+c]*x0 + fw1T[ci*16+c]*x1;
            g += gw0T[ci*16+c]*x0 + gw1T[ci*16+c]*x1;
        }
        float vv = tanhf(f) * sigm(g);
        s_xg[pc*12 + l] = vv;   // reuse xg buffer for gate output
        g_XG[(size_t)(vb0+p)*16*nLout + c*nLout + l] = vv;
    }
    __syncthreads();
    if (tid < 128) {
        int c = tid & 15, p = tid >> 4;
        float s = sb2[c];
        #pragma unroll
        for (int ci = 0; ci < 16; ci++) s += swT[ci*16+c] * s_xg[(p*16+ci)*12 + nLout - 1];
        g_skip[(size_t)(vb0+p)*16 + c] += s;
    }
}

// -------------------- end head : 16 pairs/block --------------------
__global__ __launch_bounds__(256) void end_kernel(const float* __restrict__ end1_W,
        const float* __restrict__ end1_b, const float* __restrict__ end2_W,
        const float* __restrict__ end2_b, float* __restrict__ out) {
    __shared__ float o1[16][16], o2[16][17];
    __shared__ float e1[256], e2[192], b1[16], b2[12];
    int tid = threadIdx.x;
    int vb0 = blockIdx.x * 16;
    for (int i = tid; i < 256; i += 256) e1[i] = end1_W[i];
    if (tid < 192) e2[tid] = end2_W[tid];
    if (tid < 16) b1[tid] = end1_b[tid];
    if (tid < 12) b2[tid] = end2_b[tid];
    int t = tid & 15, p = tid >> 4;
    o1[p][t] = fmaxf(g_skip[(size_t)(vb0+p)*16 + t], 0.f);
    __syncthreads();
    float a = b1[t];
    #pragma unroll
    for (int ci = 0; ci < 16; ci++) a += e1[t*16+ci] * o1[p][ci];
    o2[p][t] = fmaxf(a, 0.f);
    __syncthreads();
    if (t < HORC) {
        float r = b2[t];
        #pragma unroll
        for (int c = 0; c < 16; c++) r += e2[t*16+c] * o2[p][c];
        int vb = vb0 + p; int v = vb >> 5, b = vb & 31;
        out[((size_t)b*HORC + t)*VV + v] = r;
    }
}

__global__ void adjcopy_kernel(float* __restrict__ out) {
    int i = blockIdx.x * 256 + threadIdx.x;
    if (i < VV*VV) out[i] = g_adj[i];
}

// -------------------- launch --------------------
extern "C" void kernel_launch(void* const* d_in, const int* in_sizes, int n_in,
                              void* d_out, int out_size) {
    const float* input    = (const float*)d_in[0];
    const float* start_W  = (const float*)d_in[1];
    const float* start_b  = (const float*)d_in[2];
    const float* filt_W   = (const float*)d_in[3];
    const float* filt_b   = (const float*)d_in[4];
    const float* gate_W   = (const float*)d_in[5];
    const float* gate_b   = (const float*)d_in[6];
    const float* skip_W   = (const float*)d_in[7];
    const float* skip_b   = (const float*)d_in[8];
    const float* gconv_W  = (const float*)d_in[9];
    const float* gconv_b  = (const float*)d_in[10];
    const float* bn_gamma = (const float*)d_in[11];
    const float* bn_beta  = (const float*)d_in[12];
    const float* bn_mean  = (const float*)d_in[13];
    const float* bn_var   = (const float*)d_in[14];
    const float* end1_W   = (const float*)d_in[15];
    const float* end1_b   = (const float*)d_in[16];
    const float* end2_W   = (const float*)d_in[17];
    const float* end2_b   = (const float*)d_in[18];
    const float* lin_W    = (const float*)d_in[19];
    const float* lin_b    = (const float*)d_in[20];
    const float* fc1_W    = (const float*)d_in[21];
    const float* fc1_b    = (const float*)d_in[22];
    const float* fc2_W    = (const float*)d_in[23];
    const float* fc2_b    = (const float*)d_in[24];
    const float* fc3_W    = (const float*)d_in[25];
    const float* fc3_b    = (const float*)d_in[26];
    float* out = (float*)d_out;

    setup_kernel<<<64, 256>>>(lin_W, fc1_W, fc1_b, fc2_W, fc2_b, fc3_W, fc3_b,
                              gconv_W, bn_gamma, bn_beta, bn_mean, bn_var);
    trig_kernel<<<(257*512 + 255)/256, 256>>>();
    fftlin_kernel<<<BB*VV/128, 256>>>(input, lin_b);
    irfft2_kernel<<<dim3(4, BB), 256>>>();
    adj_part_kernel<<<dim3(VV/64, VV/32, 4), 256>>>();
    adj_final_kernel<<<VV*VV/256, 256>>>();
    transpose_kernel<<<dim3(16, 16), dim3(32, 8)>>>();
    gemm_a2<<<dim3(4, 4), 256>>>();
    start_gate_kernel<<<VV*BB/8, 256>>>(input, start_W, start_b,
                                        filt_W, filt_b, gate_W, gate_b, skip_W, skip_b);

    static const int dils[NLC] = {1, 2, 1, 2, 1, 2, 1, 2};
    int L = 13;
    int Lo = 12;
    for (int i = 0; i < 7; i++) {
        int N = BB * CHC * Lo;
        gemm_layer<<<dim3(N/128, 8), 256>>>(N);
        int nLo = Lo - dils[i+1];
        comb_gate_kernel<<<VV*BB/8, 256>>>(i, L, Lo, dils[i], i & 1, nLo, dils[i+1],
                                           gconv_b, filt_W, filt_b, gate_W, gate_b,
                                           skip_W, skip_b);
        L = Lo; Lo = nLo;
    }
    end_kernel<<<VV*BB/16, 256>>>(end1_W, end1_b, end2_W, end2_b, out);
    if (out_size >= BB*HORC*VV + VV*VV)
        adjcopy_kernel<<<(VV*VV + 255)/256, 256>>>(out + BB*HORC*VV);
}

// round 13
// speedup vs baseline: 1.9352x; 1.2205x over previous
#include <cuda_runtime.h>
#include <math.h>

#define BB  32
#define VV  512
#define TT  12
#define FINC 2
#define DGC 20
#define CHC 16
#define HORC 12
#define NLC 8
#define EPSC 0.3f
#define RFC 13

// -------------------- device scratch (static, no allocation) --------------------
__device__ float g_XA[VV*BB*CHC*13];
__device__ float g_XB[VV*BB*CHC*13];
__device__ float g_XG[VV*BB*CHC*13];
__device__ float g_P [VV*BB*CHC*13];
__device__ float g_Q [VV*BB*CHC*13];
__device__ float g_skip[VV*BB*CHC];
__device__ float g_real[BB*VV*DGC];
__device__ float g_img [BB*VV*DGC];
__device__ float g_feat[BB*VV*60];
__device__ float g_adj [VV*VV];
__device__ float g_adjT[VV*VV];
__device__ float g_A2  [VV*VV];
__device__ float g_part[4*VV*VV];
__device__ float g_Tct[257*VV], g_Tst[257*VV];
__device__ float g_Cw[DGC*24], g_Sw[DGC*24];
__device__ float4 g_wcT4[15*VV];     // [jc][w] transposed fc-weight chunks
__device__ float g_bc[VV];
__device__ float g_WX[NLC*CHC*CHC], g_WP[NLC*CHC*CHC], g_WQ[NLC*CHC*CHC];
__device__ float g_bnsc[NLC*CHC], g_bnsh[NLC*CHC];

__device__ __forceinline__ float sigm(float x) { return 1.f / (1.f + expf(-x)); }

// -------------------- setup: fold constants (all-float trig) --------------------
__global__ void setup_kernel(const float* __restrict__ lin_W,
                             const float* __restrict__ fc1_W, const float* __restrict__ fc1_b,
                             const float* __restrict__ fc2_W, const float* __restrict__ fc2_b,
                             const float* __restrict__ fc3_W, const float* __restrict__ fc3_b,
                             const float* __restrict__ gconv_W,
                             const float* __restrict__ bn_gamma, const float* __restrict__ bn_beta,
                             const float* __restrict__ bn_mean, const float* __restrict__ bn_var) {
    int idx0 = blockIdx.x * blockDim.x + threadIdx.x;
    int stride = gridDim.x * blockDim.x;
    // irfft trig table: Tct[k][m] = w_k * cos(2pi k m/512)/512
    for (int i = idx0; i < 257*512; i += stride) {
        int k = i >> 9, m = i & 511;
        float w = (k == 0 || k == 256) ? (1.f/512.f) : (2.f/512.f);
        int a = (k * m) & 511;
        float sn, cs;
        sincospif((float)a * (2.f/512.f), &sn, &cs);
        g_Tct[i] = w * cs;
        g_Tst[i] = w * sn;
    }
    for (int i = idx0; i < DGC*24; i += stride) {
        int d = i / 24, n = i % 24;
        float csum = 0.f, ssum = 0.f;
        for (int j = 0; j < 24; j++) {
            float sn, cs;
            sincospif((float)((j*n) % 24) * (1.f/12.f), &sn, &cs);
            csum += lin_W[d*24+j] * cs;
            ssum += lin_W[d*24+j] * (-sn);
        }
        g_Cw[i] = csum; g_Sw[i] = ssum;
    }
    // transposed fc weights: g_wcT4[jc*512 + w].e = wc[w][jc*4+e]
    for (int i = idx0; i < 15*VV; i += stride) {
        int jc = i / VV, w = i % VV;
        float4 v;
        float* ve = (float*)&v;
        #pragma unroll
        for (int e = 0; e < 4; e++) {
            int j = jc*4 + e;
            ve[e] = (j < 20) ? fc1_W[w*20+j] : (j < 40) ? fc2_W[w*20+j-20] : fc3_W[w*20+j-40];
        }
        g_wcT4[i] = v;
    }
    for (int i = idx0; i < VV; i += stride) g_bc[i] = fc1_b[i] + fc2_b[i] + fc3_b[i];
    for (int i = idx0; i < NLC*256; i += stride) {
        int L = i >> 8, ci = i & 15, co = (i >> 4) & 15;
        const float* G = gconv_W + (size_t)(L*16 + co)*64;
        float w1 = G[ci], w2 = G[16+ci], w3 = G[32+ci], w4 = G[48+ci];
        g_WX[i] = EPSC*(w1+w3) + EPSC*EPSC*(w2+w4);
        g_WP[i] = (w1 - w3) + 2.f*EPSC*(w2 - w4);
        g_WQ[i] = w2 + w4;
    }
    for (int i = idx0; i < NLC*CHC; i += stride) {
        float sc = bn_gamma[i] / sqrtf(bn_var[i] + 1e-5f);
        g_bnsc[i] = sc;
        g_bnsh[i] = bn_beta[i] - bn_mean[i]*sc;
    }
}

// -------------------- DFT(24) folded into linear layer, 128 pairs/block --------------------
__global__ __launch_bounds__(256) void fftlin_kernel(const float* __restrict__ input,
                                                     const float* __restrict__ lin_b) {
    __shared__ float xr[128*25];
    __shared__ float sCw[480], sSw[480], sb[20];
    int tid = threadIdx.x;
    int p0 = blockIdx.x * 128;           // pair index = b*512 + v
    int b = p0 >> 9, v0 = p0 & 511;
    for (int i = tid; i < 480; i += 256) { sCw[i] = g_Cw[i]; sSw[i] = g_Sw[i]; }
    if (tid < 20) sb[tid] = lin_b[tid];
    {
        int f = tid & 1, pl = tid >> 1;
        #pragma unroll
        for (int tt = 0; tt < 12; tt++) {
            float val = input[((size_t)(tt*32 + b)*512 + v0)*2 + tid];
            xr[pl*25 + tt*2 + f] = val;
        }
    }
    __syncthreads();
    int ml = tid & 127, dh = tid >> 7, d0 = dh * 10;
    float re[10], im[10];
    #pragma unroll
    for (int i = 0; i < 10; i++) { re[i] = sb[d0+i]; im[i] = sb[d0+i]; }
    #pragma unroll
    for (int n = 0; n < 24; n++) {
        float x = xr[ml*25 + n];
        #pragma unroll
        for (int i = 0; i < 10; i++) {
            re[i] += x * sCw[(d0+i)*24 + n];
            im[i] += x * sSw[(d0+i)*24 + n];
        }
    }
    size_t base = (size_t)(p0 + ml) * 20 + d0;
    size_t fb = (size_t)(p0 + ml) * 60 + d0;
    #pragma unroll
    for (int i = 0; i < 10; i++) {
        g_real[base + i] = re[i];
        g_img [base + i] = im[i];
        g_feat[fb + 20 + i] = sqrtf(re[i]*re[i] + im[i]*im[i]);
        g_feat[fb + 40 + i] = atanf(re[i] / (im[i] + 1e-4f));
    }
}

// -------------------- irfft as fully shared-staged tiled GEMM --------------------
// grid (8 m-tiles of 64, 32 batches); out[b][m][d] = sum_k Tct[k][m]*R[b][k][d] - Tst*I
__global__ __launch_bounds__(256) void irfft2_kernel() {
    __shared__ float Rs[32*20], Is[32*20];
    __shared__ float Tc[32*64], Ts[32*64];
    int b = blockIdx.y;
    int m0 = blockIdx.x * 64;
    int tid = threadIdx.x;
    int ml = tid & 63, dh = tid >> 6, d0 = dh * 5;   // 64 m-lanes x 4 d-groups of 5
    const float* Rg = g_real + (size_t)b * 512 * 20;
    const float* Ig = g_img  + (size_t)b * 512 * 20;
    float acc[5] = {0.f, 0.f, 0.f, 0.f, 0.f};
    for (int k0 = 0; k0 < 257; k0 += 32) {
        int kmax = min(32, 257 - k0);
        __syncthreads();
        for (int i = tid; i < 640; i += 256) {
            int k = k0 + i / 20;
            Rs[i] = (k < 257) ? Rg[(size_t)k*20 + i%20] : 0.f;
            Is[i] = (k < 257) ? Ig[(size_t)k*20 + i%20] : 0.f;
        }
        for (int i = tid; i < kmax*64; i += 256) {
            int k = k0 + (i >> 6);
            Tc[i] = g_Tct[(size_t)k*512 + m0 + (i & 63)];
            Ts[i] = g_Tst[(size_t)k*512 + m0 + (i & 63)];
        }
        __syncthreads();
        for (int kk = 0; kk < kmax; kk++) {
            float tc = Tc[kk*64 + ml], ts = Ts[kk*64 + ml];
            #pragma unroll
            for (int i = 0; i < 5; i++)
                acc[i] += tc * Rs[kk*20 + d0 + i] - ts * Is[kk*20 + d0 + i];
        }
    }
    size_t fb = ((size_t)b*512 + m0 + ml) * 60 + d0;
    #pragma unroll
    for (int i = 0; i < 5; i++) g_feat[fb + i] = acc[i];
}

// -------------------- adj partial sums: float4 j-chunks, hoisted weights --------------------
__global__ __launch_bounds__(256) void adj_part_kernel() {
    __shared__ float4 sW[15][64];     // WsT chunk for this block's 64 w
    __shared__ float4 sF[32][15];     // feature rows for 32 v
    __shared__ float bcs[64];
    int bw = blockIdx.x * 64, bv = blockIdx.y * 32, bg = blockIdx.z;
    int tid = threadIdx.x;
    for (int i = tid; i < 15*64; i += 256) {
        int jc = i >> 6, w = i & 63;
        sW[jc][w] = g_wcT4[jc*VV + bw + w];
    }
    if (tid < 64) bcs[tid] = g_bc[bw + tid];
    float acc[8] = {0,0,0,0,0,0,0,0};
    int w = tid & 63, vg = tid >> 6;
    for (int b = bg*8; b < bg*8 + 8; b++) {
        __syncthreads();
        for (int i = tid; i < 32*15; i += 256) {
            int v = i / 15, jc = i % 15;
            sF[v][jc] = ((const float4*)(g_feat + ((size_t)b*VV + bv + v)*60))[jc];
        }
        __syncthreads();
        float d[8];
        #pragma unroll
        for (int s = 0; s < 8; s++) d[s] = bcs[w];
        #pragma unroll
        for (int jc = 0; jc < 15; jc++) {
            float4 wv = sW[jc][w];
            #pragma unroll
            for (int s = 0; s < 8; s++) {
                float4 fv = sF[vg + 4*s][jc];
                d[s] += wv.x*fv.x + wv.y*fv.y + wv.z*fv.z + wv.w*fv.w;
            }
        }
        #pragma unroll
        for (int s = 0; s < 8; s++) acc[s] += sigm(d[s] * (1.f/3.f));
    }
    #pragma unroll
    for (int s = 0; s < 8; s++)
        g_part[(size_t)bg*VV*VV + (size_t)(bv + vg + 4*s)*VV + bw + w] = acc[s];
}

// -------------------- adj finalize: reduce + sigmoid + transpose + output copy --------------------
__global__ void adj_finalize_kernel(float* __restrict__ out, int do_copy) {
    __shared__ float t[32][33];
    int bx = blockIdx.x*32, by = blockIdx.y*32;
    int x = threadIdx.x, y = threadIdx.y;   // 32 x 8
    #pragma unroll
    for (int i = 0; i < 32; i += 8) {
        size_t idx = (size_t)(by + y + i)*VV + bx + x;
        float s = g_part[idx] + g_part[VV*VV + idx] + g_part[2*VV*VV + idx] + g_part[3*VV*VV + idx];
        float a = sigm(s * (1.f/BB));
        g_adj[idx] = a;
        if (do_copy) out[idx] = a;
        t[y+i][x] = a;
    }
    __syncthreads();
    #pragma unroll
    for (int i = 0; i < 32; i += 8)
        g_adjT[(size_t)(bx + y + i)*VV + by + x] = t[x][y+i];
}

// -------------------- FFMA2 GEMM tile, double-buffered smem --------------------
__device__ __forceinline__ void gemm_tile_f2(const float* __restrict__ A, const float* __restrict__ Bm,
                                             float* __restrict__ C, int N, int bm, int bn) {
    __shared__ float AsD[2][8][256];
    __shared__ float Bs[2][8][128];
    int tid = threadIdx.x;
    int tm = (tid >> 4) * 8;
    int tn = (tid & 15) * 8;
    int lr = tid >> 5;
    int lc = (tid & 31) * 4;
    unsigned long long acc[8][4];
    #pragma unroll
    for (int i = 0; i < 8; i++)
        #pragma unroll
        for (int j = 0; j < 4; j++) acc[i][j] = 0ull;
    float4 pa = *(const float4*)&A [(size_t)lr*VV + bm + lc];
    float4 pb = *(const float4*)&Bm[(size_t)lr*N  + bn + lc];
    AsD[0][lr][2*lc+0] = pa.x; AsD[0][lr][2*lc+1] = pa.x;
    AsD[0][lr][2*lc+2] = pa.y; AsD[0][lr][2*lc+3] = pa.y;
    AsD[0][lr][2*lc+4] = pa.z; AsD[0][lr][2*lc+5] = pa.z;
    AsD[0][lr][2*lc+6] = pa.w; AsD[0][lr][2*lc+7] = pa.w;
    *(float4*)&Bs[0][lr][lc] = pb;
    __syncthreads();
    for (int k0 = 0; k0 < 512; k0 += 8) {
        int cur = (k0 >> 3) & 1;
        bool more = (k0 + 8) < 512;
        if (more) {
            pa = *(const float4*)&A [(size_t)(k0+8+lr)*VV + bm + lc];
            pb = *(const float4*)&Bm[(size_t)(k0+8+lr)*N  + bn + lc];
        }
        #pragma unroll
        for (int kk = 0; kk < 8; kk++) {
            unsigned long long av[8], xv[4];
            const unsigned long long* ap = (const unsigned long long*)&AsD[cur][kk][2*tm];
            const unsigned long long* xp = (const unsigned long long*)&Bs[cur][kk][tn];
            #pragma unroll
            for (int i = 0; i < 8; i++) av[i] = ap[i];
            #pragma unroll
            for (int j = 0; j < 4; j++) xv[j] = xp[j];
            #pragma unroll
            for (int i = 0; i < 8; i++)
                #pragma unroll
                for (int j = 0; j < 4; j++)
                    asm("fma.rn.f32x2 %0, %1, %2, %0;" : "+l"(acc[i][j]) : "l"(av[i]), "l"(xv[j]));
        }
        if (more) {
            int nxt = cur ^ 1;
            AsD[nxt][lr][2*lc+0] = pa.x; AsD[nxt][lr][2*lc+1] = pa.x;
            AsD[nxt][lr][2*lc+2] = pa.y; AsD[nxt][lr][2*lc+3] = pa.y;
            AsD[nxt][lr][2*lc+4] = pa.z; AsD[nxt][lr][2*lc+5] = pa.z;
            AsD[nxt][lr][2*lc+6] = pa.w; AsD[nxt][lr][2*lc+7] = pa.w;
            *(float4*)&Bs[nxt][lr][lc] = pb;
        }
        __syncthreads();
    }
    #pragma unroll
    for (int i = 0; i < 8; i++) {
        unsigned long long* cp = (unsigned long long*)&C[(size_t)(bm + tm + i)*N + bn + tn];
        #pragma unroll
        for (int j = 0; j < 4; j++) cp[j] = acc[i][j];
    }
}

__global__ __launch_bounds__(256) void gemm_layer(int N) {
    int by = blockIdx.y;
    const float* A = (by < 4) ? g_adj : g_A2;
    float* C = (by < 4) ? g_P : g_Q;
    gemm_tile_f2(A, g_XG, C, N, (by & 3) * 128, blockIdx.x * 128);
}

__global__ __launch_bounds__(256) void gemm_a2() {
    gemm_tile_f2(g_adjT, g_adj, g_A2, VV, blockIdx.y * 128, blockIdx.x * 128);
}

// -------------------- start conv + gate(0) + skip init : 8 pairs/block --------------------
__global__ __launch_bounds__(256) void start_gate_kernel(const float* __restrict__ input,
        const float* __restrict__ start_W, const float* __restrict__ start_b,
        const float* __restrict__ filt_W, const float* __restrict__ filt_b,
        const float* __restrict__ gate_W, const float* __restrict__ gate_b,
        const float* __restrict__ skip_W, const float* __restrict__ skip_b) {
    __shared__ float xin[8*2*13];
    __shared__ float s_xn[8*16*13];
    __shared__ float fw0T[256], fw1T[256], gw0T[256], gw1T[256], swT[256];
    __shared__ float sW[32], sB[16], fb[16], gb[16], sb2[16];
    int tid = threadIdx.x;
    int vb0 = blockIdx.x * 8;
    for (int i = tid; i < 256; i += 256) {
        int c = i & 15, ci = i >> 4;
        fw0T[i] = filt_W[(c*16+ci)*2];
        fw1T[i] = filt_W[(c*16+ci)*2+1];
        gw0T[i] = gate_W[(c*16+ci)*2];
        gw1T[i] = gate_W[(c*16+ci)*2+1];
        swT[i]  = skip_W[c*16+ci];
    }
    if (tid < 32) sW[tid] = start_W[tid];
    if (tid < 16) { sB[tid] = start_b[tid]; fb[tid] = filt_b[tid]; gb[tid] = gate_b[tid]; sb2[tid] = skip_b[tid]; }
    for (int i = tid; i < 8*2*13; i += 256) {
        int l = i % 13, pf = i / 13, f = pf & 1, p = pf >> 1;
        int vb = vb0 + p; int v = vb >> 5, b = vb & 31;
        xin[i] = (l == 0) ? 0.f : input[((((size_t)(l-1))*32 + b)*512 + v)*2 + f];
    }
    __syncthreads();
    for (int i = tid; i < 8*16*13; i += 256) {
        int l = i % 13, pc = i / 13, c = pc & 15, p = pc >> 4;
        float val = sB[c] + sW[c*2]*xin[(p*2)*13 + l] + sW[c*2+1]*xin[(p*2+1)*13 + l];
        s_xn[pc*13 + l] = val;
        g_XA[(size_t)(vb0 + p)*16*13 + c*13 + l] = val;
    }
    __syncthreads();
    for (int i = tid; i < 8*16*12; i += 256) {
        int l = i % 12, pc = i / 12, c = pc & 15, p = pc >> 4;
        float f = fb[c], g = gb[c];
        #pragma unroll
        for (int ci = 0; ci < 16; ci++) {
            float x0 = s_xn[(p*16+ci)*13 + l], x1 = s_xn[(p*16+ci)*13 + l + 1];
            f += fw0T[ci*16+c]*x0 + fw1T[ci*16+c]*x1;
            g += gw0T[ci*16+c]*x0 + gw1T[ci*16+c]*x1;
        }
        float vv = tanhf(f) * sigm(g);
        g_XG[(size_t)(vb0 + p)*16*12 + c*12 + l] = vv;
        if (l == 11) xin[pc] = vv;   // stash tail for skip
    }
    __syncthreads();
    if (tid < 128) {
        int c = tid & 15, p = tid >> 4;
        float s = sb2[c];
        #pragma unroll
        for (int ci = 0; ci < 16; ci++) s += swT[ci*16+c] * xin[p*16+ci];
        g_skip[(size_t)(vb0 + p)*16 + c] = s;
    }
}

// -------------------- fused combine(layer) + gate(layer+1) + skip : 8 pairs/block --------------------
__global__ __launch_bounds__(256) void comb_gate_kernel(int layer, int Lin, int Lout, int dil,
        int flip, int nLout, int ndil,
        const float* __restrict__ gconv_b,
        const float* __restrict__ filt_W, const float* __restrict__ filt_b,
        const float* __restrict__ gate_W, const float* __restrict__ gate_b,
        const float* __restrict__ skip_W, const float* __restrict__ skip_b) {
    int nlayer = layer + 1;
    const float* Xres = flip ? g_XB : g_XA;
    float* Xout = flip ? g_XA : g_XB;
    __shared__ float s_xg[8*16*12], s_pp[8*16*12], s_qq[8*16*12], s_xn[8*16*12];
    __shared__ float wxT[256], wpT[256], wqT[256], swT[256];
    __shared__ float fw0T[256], fw1T[256], gw0T[256], gw1T[256];
    __shared__ float gcb[16], bnsc[16], bnsh[16], fb[16], gb[16], sb2[16];
    int tid = threadIdx.x;
    int vb0 = blockIdx.x * 8;
    for (int i = tid; i < 256; i += 256) {
        int c = i & 15, ci = i >> 4;
        wxT[i] = g_WX[layer*256 + c*16+ci];
        wpT[i] = g_WP[layer*256 + c*16+ci];
        wqT[i] = g_WQ[layer*256 + c*16+ci];
        swT[i] = skip_W[nlayer*256 + c*16+ci];
        fw0T[i] = filt_W[nlayer*512 + (c*16+ci)*2];
        fw1T[i] = filt_W[nlayer*512 + (c*16+ci)*2+1];
        gw0T[i] = gate_W[nlayer*512 + (c*16+ci)*2];
        gw1T[i] = gate_W[nlayer*512 + (c*16+ci)*2+1];
    }
    if (tid < 16) {
        gcb[tid]  = gconv_b[layer*16+tid];
        bnsc[tid] = g_bnsc[layer*16+tid];
        bnsh[tid] = g_bnsh[layer*16+tid];
        fb[tid]   = filt_b[nlayer*16+tid];
        gb[tid]   = gate_b[nlayer*16+tid];
        sb2[tid]  = skip_b[nlayer*16+tid];
    }
    {
        const float* srcX = g_XG + (size_t)vb0*16*Lout;
        const float* srcP = g_P  + (size_t)vb0*16*Lout;
        const float* srcQ = g_Q  + (size_t)vb0*16*Lout;
        int nload = 8*16*Lout;
        for (int i = tid; i < nload; i += 256) {
            int l = i % Lout, pc = i / Lout;
            s_xg[pc*12 + l] = srcX[i];
            s_pp[pc*12 + l] = srcP[i];
            s_qq[pc*12 + l] = srcQ[i];
        }
    }
    __syncthreads();
    for (int i = tid; i < 8*16*Lout; i += 256) {
        int l = i % Lout, pc = i / Lout, c = pc & 15, p = pc >> 4;
        float h = gcb[c];
        #pragma unroll
        for (int ci = 0; ci < 16; ci++) {
            int a = (p*16+ci)*12 + l;
            h += wxT[ci*16+c]*s_xg[a] + wpT[ci*16+c]*s_pp[a] + wqT[ci*16+c]*s_qq[a];
        }
        float res = Xres[(size_t)(vb0+p)*16*Lin + c*Lin + l + dil];
        float xv = (h + res) * bnsc[c] + bnsh[c];
        s_xn[pc*12 + l] = xv;
        if (layer < 6) Xout[(size_t)(vb0+p)*16*Lout + c*Lout + l] = xv;
    }
    __syncthreads();
    for (int i = tid; i < 8*16*nLout; i += 256) {
        int l = i % nLout, pc = i / nLout, c = pc & 15, p = pc >> 4;
        float f = fb[c], g = gb[c];
        #pragma unroll
        for (int ci = 0; ci < 16; ci++) {
            int a = (p*16+ci)*12 + l;
            float x0 = s_xn[a], x1 = s_xn[a + ndil];
            f += fw0T[ci*16+c]*x0 + fw1T[ci*16+c]*x1;
            g += gw0T[ci*16+c]*x0 + gw1T[ci*16+c]*x1;
        }
        float vv = tanhf(f) * sigm(g);
        s_xg[pc*12 + l] = vv;   // reuse xg buffer for gate output
        g_XG[(size_t)(vb0+p)*16*nLout + c*nLout + l] = vv;
    }
    __syncthreads();
    if (tid < 128) {
        int c = tid & 15, p = tid >> 4;
        float s = sb2[c];
        #pragma unroll
        for (int ci = 0; ci < 16; ci++) s += swT[ci*16+c] * s_xg[(p*16+ci)*12 + nLout - 1];
        g_skip[(size_t)(vb0+p)*16 + c] += s;
    }
}

// -------------------- end head : 16 pairs/block --------------------
__global__ __launch_bounds__(256) void end_kernel(const float* __restrict__ end1_W,
        const float* __restrict__ end1_b, const float* __restrict__ end2_W,
        const float* __restrict__ end2_b, float* __restrict__ out) {
    __shared__ float o1[16][16], o2[16][17];
    __shared__ float e1[256], e2[192], b1[16], b2[12];
    int tid = threadIdx.x;
    int vb0 = blockIdx.x * 16;
    for (int i = tid; i < 256; i += 256) e1[i] = end1_W[i];
    if (tid < 192) e2[tid] = end2_W[tid];
    if (tid < 16) b1[tid] = end1_b[tid];
    if (tid < 12) b2[tid] = end2_b[tid];
    int t = tid & 15, p = tid >> 4;
    o1[p][t] = fmaxf(g_skip[(size_t)(vb0+p)*16 + t], 0.f);
    __syncthreads();
    float a = b1[t];
    #pragma unroll
    for (int ci = 0; ci < 16; ci++) a += e1[t*16+ci] * o1[p][ci];
    o2[p][t] = fmaxf(a, 0.f);
    __syncthreads();
    if (t < HORC) {
        float r = b2[t];
        #pragma unroll
        for (int c = 0; c < 16; c++) r += e2[t*16+c] * o2[p][c];
        int vb = vb0 + p; int v = vb >> 5, b = vb & 31;
        out[((size_t)b*HORC + t)*VV + v] = r;
    }
}

// -------------------- launch --------------------
extern "C" void kernel_launch(void* const* d_in, const int* in_sizes, int n_in,
                              void* d_out, int out_size) {
    const float* input    = (const float*)d_in[0];
    const float* start_W  = (const float*)d_in[1];
    const float* start_b  = (const float*)d_in[2];
    const float* filt_W   = (const float*)d_in[3];
    const float* filt_b   = (const float*)d_in[4];
    const float* gate_W   = (const float*)d_in[5];
    const float* gate_b   = (const float*)d_in[6];
    const float* skip_W   = (const float*)d_in[7];
    const float* skip_b   = (const float*)d_in[8];
    const float* gconv_W  = (const float*)d_in[9];
    const float* gconv_b  = (const float*)d_in[10];
    const float* bn_gamma = (const float*)d_in[11];
    const float* bn_beta  = (const float*)d_in[12];
    const float* bn_mean  = (const float*)d_in[13];
    const float* bn_var   = (const float*)d_in[14];
    const float* end1_W   = (const float*)d_in[15];
    const float* end1_b   = (const float*)d_in[16];
    const float* end2_W   = (const float*)d_in[17];
    const float* end2_b   = (const float*)d_in[18];
    const float* lin_W    = (const float*)d_in[19];
    const float* lin_b    = (const float*)d_in[20];
    const float* fc1_W    = (const float*)d_in[21];
    const float* fc1_b    = (const float*)d_in[22];
    const float* fc2_W    = (const float*)d_in[23];
    const float* fc2_b    = (const float*)d_in[24];
    const float* fc3_W    = (const float*)d_in[25];
    const float* fc3_b    = (const float*)d_in[26];
    float* out = (float*)d_out;

    int do_copy = (out_size >= BB*HORC*VV + VV*VV) ? 1 : 0;

    setup_kernel<<<128, 256>>>(lin_W, fc1_W, fc1_b, fc2_W, fc2_b, fc3_W, fc3_b,
                               gconv_W, bn_gamma, bn_beta, bn_mean, bn_var);
    fftlin_kernel<<<BB*VV/128, 256>>>(input, lin_b);
    irfft2_kernel<<<dim3(8, BB), 256>>>();
    adj_part_kernel<<<dim3(VV/64, VV/32, 4), 256>>>();
    adj_finalize_kernel<<<dim3(16, 16), dim3(32, 8)>>>(out + BB*HORC*VV, do_copy);
    gemm_a2<<<dim3(4, 4), 256>>>();
    start_gate_kernel<<<VV*BB/8, 256>>>(input, start_W, start_b,
                                        filt_W, filt_b, gate_W, gate_b, skip_W, skip_b);

    static const int dils[NLC] = {1, 2, 1, 2, 1, 2, 1, 2};
    int L = 13;
    int Lo = 12;
    for (int i = 0; i < 7; i++) {
        int N = BB * CHC * Lo;
        gemm_layer<<<dim3(N/128, 8), 256>>>(N);
        int nLo = Lo - dils[i+1];
        comb_gate_kernel<<<VV*BB/8, 256>>>(i, L, Lo, dils[i], i & 1, nLo, dils[i+1],
                                           gconv_b, filt_W, filt_b, gate_W, gate_b,
                                           skip_W, skip_b);
        L = Lo; Lo = nLo;
    }
    end_kernel<<<VV*BB/16, 256>>>(end1_W, end1_b, end2_W, end2_b, out);
}

// round 15
// speedup vs baseline: 2.1366x; 1.1041x over previous
#include <cuda_runtime.h>
#include <math.h>

#define BB  32
#define VV  512
#define TT  12
#define FINC 2
#define DGC 20
#define CHC 16
#define HORC 12
#define NLC 8
#define EPSC 0.3f
#define RFC 13

// -------------------- device scratch (static, no allocation) --------------------
__device__ float g_XA[VV*BB*CHC*13];
__device__ float g_XB[VV*BB*CHC*13];
__device__ float g_XG[VV*BB*CHC*13];
__device__ float g_P [VV*BB*CHC*13];
__device__ float g_Q [VV*BB*CHC*13];
__device__ float g_skip[VV*BB*CHC];
__device__ float g_real[BB*VV*DGC];
__device__ float g_img [BB*VV*DGC];
__device__ float g_feat[BB*VV*60];
__device__ float g_adj [VV*VV];
__device__ float g_adjT[VV*VV];
__device__ float g_A2T [VV*VV];
__device__ float g_part[4*VV*VV];
__device__ float g_Tct[257*VV], g_Tst[257*VV];
__device__ float g_Cw[DGC*24], g_Sw[DGC*24];
__device__ float4 g_wcT4[15*VV];
__device__ float g_bc[VV];
__device__ float g_WX[NLC*CHC*CHC], g_WP[NLC*CHC*CHC], g_WQ[NLC*CHC*CHC];
__device__ float g_bnsc[NLC*CHC], g_bnsh[NLC*CHC];

__device__ __forceinline__ float sigm(float x) { return 1.f / (1.f + expf(-x)); }
__device__ __forceinline__ unsigned tf32cvt(float f) {
    unsigned u; asm("cvt.rna.tf32.f32 %0, %1;" : "=r"(u) : "f"(f)); return u;
}

#define MMA_TF32(D, A, B) \
    asm volatile( \
        "mma.sync.aligned.m16n8k8.row.col.f32.tf32.tf32.f32 " \
        "{%0,%1,%2,%3}, {%4,%5,%6,%7}, {%8,%9}, {%0,%1,%2,%3};" \
        : "+f"((D)[0]), "+f"((D)[1]), "+f"((D)[2]), "+f"((D)[3]) \
        : "r"((A)[0]), "r"((A)[1]), "r"((A)[2]), "r"((A)[3]), \
          "r"((B)[0]), "r"((B)[1]))

// -------------------- setup: fold constants (all-float trig) --------------------
__global__ void setup_kernel(const float* __restrict__ lin_W,
                             const float* __restrict__ fc1_W, const float* __restrict__ fc1_b,
                             const float* __restrict__ fc2_W, const float* __restrict__ fc2_b,
                             const float* __restrict__ fc3_W, const float* __restrict__ fc3_b,
                             const float* __restrict__ gconv_W,
                             const float* __restrict__ bn_gamma, const float* __restrict__ bn_beta,
                             const float* __restrict__ bn_mean, const float* __restrict__ bn_var) {
    int idx0 = blockIdx.x * blockDim.x + threadIdx.x;
    int stride = gridDim.x * blockDim.x;
    for (int i = idx0; i < 257*512; i += stride) {
        int k = i >> 9, m = i & 511;
        float w = (k == 0 || k == 256) ? (1.f/512.f) : (2.f/512.f);
        int a = (k * m) & 511;
        float sn, cs;
        sincospif((float)a * (2.f/512.f), &sn, &cs);
        g_Tct[i] = w * cs;
        g_Tst[i] = w * sn;
    }
    for (int i = idx0; i < DGC*24; i += stride) {
        int d = i / 24, n = i % 24;
        float csum = 0.f, ssum = 0.f;
        for (int j = 0; j < 24; j++) {
            float sn, cs;
            sincospif((float)((j*n) % 24) * (1.f/12.f), &sn, &cs);
            csum += lin_W[d*24+j] * cs;
            ssum += lin_W[d*24+j] * (-sn);
        }
        g_Cw[i] = csum; g_Sw[i] = ssum;
    }
    for (int i = idx0; i < 15*VV; i += stride) {
        int jc = i / VV, w = i % VV;
        float4 v;
        float* ve = (float*)&v;
        #pragma unroll
        for (int e = 0; e < 4; e++) {
            int j = jc*4 + e;
            ve[e] = (j < 20) ? fc1_W[w*20+j] : (j < 40) ? fc2_W[w*20+j-20] : fc3_W[w*20+j-40];
        }
        g_wcT4[i] = v;
    }
    for (int i = idx0; i < VV; i += stride) g_bc[i] = fc1_b[i] + fc2_b[i] + fc3_b[i];
    for (int i = idx0; i < NLC*256; i += stride) {
        int L = i >> 8, ci = i & 15, co = (i >> 4) & 15;
        const float* G = gconv_W + (size_t)(L*16 + co)*64;
        float w1 = G[ci], w2 = G[16+ci], w3 = G[32+ci], w4 = G[48+ci];
        g_WX[i] = EPSC*(w1+w3) + EPSC*EPSC*(w2+w4);
        g_WP[i] = (w1 - w3) + 2.f*EPSC*(w2 - w4);
        g_WQ[i] = w2 + w4;
    }
    for (int i = idx0; i < NLC*CHC; i += stride) {
        float sc = bn_gamma[i] / sqrtf(bn_var[i] + 1e-5f);
        g_bnsc[i] = sc;
        g_bnsh[i] = bn_beta[i] - bn_mean[i]*sc;
    }
}

// -------------------- DFT(24) folded into linear layer, 128 pairs/block --------------------
__global__ __launch_bounds__(256) void fftlin_kernel(const float* __restrict__ input,
                                                     const float* __restrict__ lin_b) {
    __shared__ float xr[128*25];
    __shared__ float sCw[480], sSw[480], sb[20];
    int tid = threadIdx.x;
    int p0 = blockIdx.x * 128;
    int b = p0 >> 9, v0 = p0 & 511;
    for (int i = tid; i < 480; i += 256) { sCw[i] = g_Cw[i]; sSw[i] = g_Sw[i]; }
    if (tid < 20) sb[tid] = lin_b[tid];
    {
        int f = tid & 1, pl = tid >> 1;
        #pragma unroll
        for (int tt = 0; tt < 12; tt++) {
            float val = input[((size_t)(tt*32 + b)*512 + v0)*2 + tid];
            xr[pl*25 + tt*2 + f] = val;
        }
    }
    __syncthreads();
    int ml = tid & 127, dh = tid >> 7, d0 = dh * 10;
    float re[10], im[10];
    #pragma unroll
    for (int i = 0; i < 10; i++) { re[i] = sb[d0+i]; im[i] = sb[d0+i]; }
    #pragma unroll
    for (int n = 0; n < 24; n++) {
        float x = xr[ml*25 + n];
        #pragma unroll
        for (int i = 0; i < 10; i++) {
            re[i] += x * sCw[(d0+i)*24 + n];
            im[i] += x * sSw[(d0+i)*24 + n];
        }
    }
    size_t base = (size_t)(p0 + ml) * 20 + d0;
    size_t fb = (size_t)(p0 + ml) * 60 + d0;
    #pragma unroll
    for (int i = 0; i < 10; i++) {
        g_real[base + i] = re[i];
        g_img [base + i] = im[i];
        g_feat[fb + 20 + i] = sqrtf(re[i]*re[i] + im[i]*im[i]);
        g_feat[fb + 40 + i] = atanf(re[i] / (im[i] + 1e-4f));
    }
}

// -------------------- irfft as fully shared-staged tiled GEMM --------------------
__global__ __launch_bounds__(256) void irfft2_kernel() {
    __shared__ float Rs[32*20], Is[32*20];
    __shared__ float Tc[32*64], Ts[32*64];
    int b = blockIdx.y;
    int m0 = blockIdx.x * 64;
    int tid = threadIdx.x;
    int ml = tid & 63, dh = tid >> 6, d0 = dh * 5;
    const float* Rg = g_real + (size_t)b * 512 * 20;
    const float* Ig = g_img  + (size_t)b * 512 * 20;
    float acc[5] = {0.f, 0.f, 0.f, 0.f, 0.f};
    for (int k0 = 0; k0 < 257; k0 += 32) {
        int kmax = min(32, 257 - k0);
        __syncthreads();
        for (int i = tid; i < 640; i += 256) {
            int k = k0 + i / 20;
            Rs[i] = (k < 257) ? Rg[(size_t)k*20 + i%20] : 0.f;
            Is[i] = (k < 257) ? Ig[(size_t)k*20 + i%20] : 0.f;
        }
        for (int i = tid; i < kmax*64; i += 256) {
            int k = k0 + (i >> 6);
            Tc[i] = g_Tct[(size_t)k*512 + m0 + (i & 63)];
            Ts[i] = g_Tst[(size_t)k*512 + m0 + (i & 63)];
        }
        __syncthreads();
        for (int kk = 0; kk < kmax; kk++) {
            float tc = Tc[kk*64 + ml], ts = Ts[kk*64 + ml];
            #pragma unroll
            for (int i = 0; i < 5; i++)
                acc[i] += tc * Rs[kk*20 + d0 + i] - ts * Is[kk*20 + d0 + i];
        }
    }
    size_t fb = ((size_t)b*512 + m0 + ml) * 60 + d0;
    #pragma unroll
    for (int i = 0; i < 5; i++) g_feat[fb + i] = acc[i];
}

// -------------------- adj partial sums: float4 j-chunks, hoisted weights --------------------
__global__ __launch_bounds__(256) void adj_part_kernel() {
    __shared__ float4 sW[15][64];
    __shared__ float4 sF[32][15];
    __shared__ float bcs[64];
    int bw = blockIdx.x * 64, bv = blockIdx.y * 32, bg = blockIdx.z;
    int tid = threadIdx.x;
    for (int i = tid; i < 15*64; i += 256) {
        int jc = i >> 6, w = i & 63;
        sW[jc][w] = g_wcT4[jc*VV + bw + w];
    }
    if (tid < 64) bcs[tid] = g_bc[bw + tid];
    float acc[8] = {0,0,0,0,0,0,0,0};
    int w = tid & 63, vg = tid >> 6;
    for (int b = bg*8; b < bg*8 + 8; b++) {
        __syncthreads();
        for (int i = tid; i < 32*15; i += 256) {
            int v = i / 15, jc = i % 15;
            sF[v][jc] = ((const float4*)(g_feat + ((size_t)b*VV + bv + v)*60))[jc];
        }
        __syncthreads();
        float d[8];
        #pragma unroll
        for (int s = 0; s < 8; s++) d[s] = bcs[w];
        #pragma unroll
        for (int jc = 0; jc < 15; jc++) {
            float4 wv = sW[jc][w];
            #pragma unroll
            for (int s = 0; s < 8; s++) {
                float4 fv = sF[vg + 4*s][jc];
                d[s] += wv.x*fv.x + wv.y*fv.y + wv.z*fv.z + wv.w*fv.w;
            }
        }
        #pragma unroll
        for (int s = 0; s < 8; s++) acc[s] += sigm(d[s] * (1.f/3.f));
    }
    #pragma unroll
    for (int s = 0; s < 8; s++)
        g_part[(size_t)bg*VV*VV + (size_t)(bv + vg + 4*s)*VV + bw + w] = acc[s];
}

// -------------------- adj finalize: reduce + sigmoid + transpose + output copy --------------------
__global__ void adj_finalize_kernel(float* __restrict__ out, int do_copy) {
    __shared__ float t[32][33];
    int bx = blockIdx.x*32, by = blockIdx.y*32;
    int x = threadIdx.x, y = threadIdx.y;   // 32 x 8
    #pragma unroll
    for (int i = 0; i < 32; i += 8) {
        size_t idx = (size_t)(by + y + i)*VV + bx + x;
        float s = g_part[idx] + g_part[VV*VV + idx] + g_part[2*VV*VV + idx] + g_part[3*VV*VV + idx];
        float a = sigm(s * (1.f/BB));
        g_adj[idx] = a;
        if (do_copy) out[idx] = a;
        t[y+i][x] = a;
    }
    __syncthreads();
    #pragma unroll
    for (int i = 0; i < 32; i += 8)
        g_adjT[(size_t)(bx + y + i)*VV + by + x] = t[x][y+i];
}

// -------------------- FFMA2 GEMM tile (exact fp32, used only for A2T) --------------------
__device__ __forceinline__ void gemm_tile_f2(const float* __restrict__ A, const float* __restrict__ Bm,
                                             float* __restrict__ C, int N, int bm, int bn) {
    __shared__ float AsD[2][8][256];
    __shared__ float Bs[2][8][128];
    int tid = threadIdx.x;
    int tm = (tid >> 4) * 8;
    int tn = (tid & 15) * 8;
    int lr = tid >> 5;
    int lc = (tid & 31) * 4;
    unsigned long long acc[8][4];
    #pragma unroll
    for (int i = 0; i < 8; i++)
        #pragma unroll
        for (int j = 0; j < 4; j++) acc[i][j] = 0ull;
    float4 pa = *(const float4*)&A [(size_t)lr*VV + bm + lc];
    float4 pb = *(const float4*)&Bm[(size_t)lr*N  + bn + lc];
    AsD[0][lr][2*lc+0] = pa.x; AsD[0][lr][2*lc+1] = pa.x;
    AsD[0][lr][2*lc+2] = pa.y; AsD[0][lr][2*lc+3] = pa.y;
    AsD[0][lr][2*lc+4] = pa.z; AsD[0][lr][2*lc+5] = pa.z;
    AsD[0][lr][2*lc+6] = pa.w; AsD[0][lr][2*lc+7] = pa.w;
    *(float4*)&Bs[0][lr][lc] = pb;
    __syncthreads();
    for (int k0 = 0; k0 < 512; k0 += 8) {
        int cur = (k0 >> 3) & 1;
        bool more = (k0 + 8) < 512;
        if (more) {
            pa = *(const float4*)&A [(size_t)(k0+8+lr)*VV + bm + lc];
            pb = *(const float4*)&Bm[(size_t)(k0+8+lr)*N  + bn + lc];
        }
        #pragma unroll
        for (int kk = 0; kk < 8; kk++) {
            unsigned long long av[8], xv[4];
            const unsigned long long* ap = (const unsigned long long*)&AsD[cur][kk][2*tm];
            const unsigned long long* xp = (const unsigned long long*)&Bs[cur][kk][tn];
            #pragma unroll
            for (int i = 0; i < 8; i++) av[i] = ap[i];
            #pragma unroll
            for (int j = 0; j < 4; j++) xv[j] = xp[j];
            #pragma unroll
            for (int i = 0; i < 8; i++)
                #pragma unroll
                for (int j = 0; j < 4; j++)
                    asm("fma.rn.f32x2 %0, %1, %2, %0;" : "+l"(acc[i][j]) : "l"(av[i]), "l"(xv[j]));
        }
        if (more) {
            int nxt = cur ^ 1;
            AsD[nxt][lr][2*lc+0] = pa.x; AsD[nxt][lr][2*lc+1] = pa.x;
            AsD[nxt][lr][2*lc+2] = pa.y; AsD[nxt][lr][2*lc+3] = pa.y;
            AsD[nxt][lr][2*lc+4] = pa.z; AsD[nxt][lr][2*lc+5] = pa.z;
            AsD[nxt][lr][2*lc+6] = pa.w; AsD[nxt][lr][2*lc+7] = pa.w;
            *(float4*)&Bs[nxt][lr][lc] = pb;
        }
        __syncthreads();
    }
    #pragma unroll
    for (int i = 0; i < 8; i++) {
        unsigned long long* cp = (unsigned long long*)&C[(size_t)(bm + tm + i)*N + bn + tn];
        #pragma unroll
        for (int j = 0; j < 4; j++) cp[j] = acc[i][j];
    }
}

// g_A2T[m][k] = (adj@adj)[k][m]  (exact fp32)
__global__ __launch_bounds__(256) void gemm_a2t() {
    gemm_tile_f2(g_adj, g_adjT, g_A2T, VV, blockIdx.y * 128, blockIdx.x * 128);
}

// -------------------- split-tf32 tensor-core layer GEMM (fp32-accurate, 3-mma) --------------------
// C[m,n] = sum_k At[m][k] * X[k][n].  Block 128m x 64n, 8 warps, k-chunk 16.
__global__ __launch_bounds__(256) void gemm_layer_mma(int N) {
    __shared__ float sAh[128][20], sAl[128][20];
    __shared__ float sBh[64][20],  sBl[64][20];
    int by = blockIdx.y;
    const float* __restrict__ At = (by < 4) ? g_adjT : g_A2T;
    float* __restrict__ C = (by < 4) ? g_P : g_Q;
    const float* __restrict__ X = g_XG;
    int bm = (by & 3) * 128;
    int bn = blockIdx.x * 64;
    int tid = threadIdx.x;
    int lane = tid & 31, warp = tid >> 5;
    int m_off = (warp & 3) * 32, n_off = (warp >> 2) * 32;
    int frow = lane >> 2, fcol = lane & 3;

    float d[2][4][4];
    #pragma unroll
    for (int mi = 0; mi < 2; mi++)
        #pragma unroll
        for (int ni = 0; ni < 4; ni++)
            #pragma unroll
            for (int e = 0; e < 4; e++) d[mi][ni][e] = 0.f;

    int am = tid >> 2, aj = (tid & 3) * 4;
    int sbn = tid & 63, bkg = (tid >> 6) * 4;

    const float* Ap0 = At + (size_t)(bm + am) * 512 + aj;
    const float* Ap1 = At + (size_t)(bm + am + 64) * 512 + aj;
    float4 ra0 = *(const float4*)Ap0;
    float4 ra1 = *(const float4*)Ap1;
    float rb[4];
    #pragma unroll
    for (int j = 0; j < 4; j++) rb[j] = X[(size_t)(bkg + j) * N + bn + sbn];

    for (int k0 = 0; k0 < 512; k0 += 16) {
        {
            const float* r0 = (const float*)&ra0;
            const float* r1 = (const float*)&ra1;
            #pragma unroll
            for (int j = 0; j < 4; j++) {
                float h0 = __uint_as_float(tf32cvt(r0[j]));
                sAh[am][aj+j] = h0;
                sAl[am][aj+j] = __uint_as_float(tf32cvt(r0[j] - h0));
                float h1 = __uint_as_float(tf32cvt(r1[j]));
                sAh[am+64][aj+j] = h1;
                sAl[am+64][aj+j] = __uint_as_float(tf32cvt(r1[j] - h1));
                float hb = __uint_as_float(tf32cvt(rb[j]));
                sBh[sbn][bkg+j] = hb;
                sBl[sbn][bkg+j] = __uint_as_float(tf32cvt(rb[j] - hb));
            }
        }
        __syncthreads();
        if (k0 + 16 < 512) {
            ra0 = *(const float4*)(Ap0 + k0 + 16);
            ra1 = *(const float4*)(Ap1 + k0 + 16);
            #pragma unroll
            for (int j = 0; j < 4; j++)
                rb[j] = X[(size_t)(k0 + 16 + bkg + j) * N + bn + sbn];
        }
        #pragma unroll
        for (int s = 0; s < 2; s++) {
            int ks = s * 8;
            unsigned ah[2][4], al[2][4];
            #pragma unroll
            for (int mi = 0; mi < 2; mi++) {
                const unsigned* h0 = (const unsigned*)&sAh[m_off + mi*16 + frow][ks + fcol];
                const unsigned* h1 = (const unsigned*)&sAh[m_off + mi*16 + frow + 8][ks + fcol];
                const unsigned* l0 = (const unsigned*)&sAl[m_off + mi*16 + frow][ks + fcol];
                const unsigned* l1 = (const unsigned*)&sAl[m_off + mi*16 + frow + 8][ks + fcol];
                ah[mi][0] = h0[0]; ah[mi][1] = h1[0]; ah[mi][2] = h0[4]; ah[mi][3] = h1[4];
                al[mi][0] = l0[0]; al[mi][1] = l1[0]; al[mi][2] = l0[4]; al[mi][3] = l1[4];
            }
            #pragma unroll
            for (int ni = 0; ni < 4; ni++) {
                unsigned bh[2], bl[2];
                const unsigned* hb = (const unsigned*)&sBh[n_off + ni*8 + frow][ks + fcol];
                const unsigned* lb = (const unsigned*)&sBl[n_off + ni*8 + frow][ks + fcol];
                bh[0] = hb[0]; bh[1] = hb[4];
                bl[0] = lb[0]; bl[1] = lb[4];
                #pragma unroll
                for (int mi = 0; mi < 2; mi++) {
                    MMA_TF32(d[mi][ni], ah[mi], bh);
                    MMA_TF32(d[mi][ni], ah[mi], bl);
                    MMA_TF32(d[mi][ni], al[mi], bh);
                }
            }
        }
        __syncthreads();
    }
    #pragma unroll
    for (int mi = 0; mi < 2; mi++) {
        int row0 = bm + m_off + mi*16 + (lane >> 2);
        #pragma unroll
        for (int ni = 0; ni < 4; ni++) {
            int col0 = bn + n_off + ni*8 + 2*(lane & 3);
            *(float2*)&C[(size_t)row0 * N + col0]       = make_float2(d[mi][ni][0], d[mi][ni][1]);
            *(float2*)&C[(size_t)(row0 + 8) * N + col0] = make_float2(d[mi][ni][2], d[mi][ni][3]);
        }
    }
}

// -------------------- start conv + gate(0) + skip init : 8 pairs/block --------------------
__global__ __launch_bounds__(256) void start_gate_kernel(const float* __restrict__ input,
        const float* __restrict__ start_W, const float* __restrict__ start_b,
        const float* __restrict__ filt_W, const float* __restrict__ filt_b,
        const float* __restrict__ gate_W, const float* __restrict__ gate_b,
        const float* __restrict__ skip_W, const float* __restrict__ skip_b) {
    __shared__ float xin[8*2*13];
    __shared__ float s_xn[8*16*13];
    __shared__ float fw0T[256], fw1T[256], gw0T[256], gw1T[256], swT[256];
    __shared__ float sW[32], sB[16], fb[16], gb[16], sb2[16];
    int tid = threadIdx.x;
    int vb0 = blockIdx.x * 8;
    for (int i = tid; i < 256; i += 256) {
        int c = i & 15, ci = i >> 4;
        fw0T[i] = filt_W[(c*16+ci)*2];
        fw1T[i] = filt_W[(c*16+ci)*2+1];
        gw0T[i] = gate_W[(c*16+ci)*2];
        gw1T[i] = gate_W[(c*16+ci)*2+1];
        swT[i]  = skip_W[c*16+ci];
    }
    if (tid < 32) sW[tid] = start_W[tid];
    if (tid < 16) { sB[tid] = start_b[tid]; fb[tid] = filt_b[tid]; gb[tid] = gate_b[tid]; sb2[tid] = skip_b[tid]; }
    for (int i = tid; i < 8*2*13; i += 256) {
        int l = i % 13, pf = i / 13, f = pf & 1, p = pf >> 1;
        int vb = vb0 + p; int v = vb >> 5, b = vb & 31;
        xin[i] = (l == 0) ? 0.f : input[((((size_t)(l-1))*32 + b)*512 + v)*2 + f];
    }
    __syncthreads();
    for (int i = tid; i < 8*16*13; i += 256) {
        int l = i % 13, pc = i / 13, c = pc & 15, p = pc >> 4;
        float val = sB[c] + sW[c*2]*xin[(p*2)*13 + l] + sW[c*2+1]*xin[(p*2+1)*13 + l];
        s_xn[pc*13 + l] = val;
        g_XA[(size_t)(vb0 + p)*16*13 + c*13 + l] = val;
    }
    __syncthreads();
    for (int i = tid; i < 8*16*12; i += 256) {
        int l = i % 12, pc = i / 12, c = pc & 15, p = pc >> 4;
        float f = fb[c], g = gb[c];
        #pragma unroll
        for (int ci = 0; ci < 16; ci++) {
            float x0 = s_xn[(p*16+ci)*13 + l], x1 = s_xn[(p*16+ci)*13 + l + 1];
            f += fw0T[ci*16+c]*x0 + fw1T[ci*16+c]*x1;
            g += gw0T[ci*16+c]*x0 + gw1T[ci*16+c]*x1;
        }
        float vv = tanhf(f) * sigm(g);
        g_XG[(size_t)(vb0 + p)*16*12 + c*12 + l] = vv;
        if (l == 11) xin[pc] = vv;
    }
    __syncthreads();
    if (tid < 128) {
        int c = tid & 15, p = tid >> 4;
        float s = sb2[c];
        #pragma unroll
        for (int ci = 0; ci < 16; ci++) s += swT[ci*16+c] * xin[p*16+ci];
        g_skip[(size_t)(vb0 + p)*16 + c] = s;
    }
}

// -------------------- fused combine(layer) + gate(layer+1) + skip : 8 pairs/block --------------------
__global__ __launch_bounds__(256) void comb_gate_kernel(int layer, int Lin, int Lout, int dil,
        int flip, int nLout, int ndil,
        const float* __restrict__ gconv_b,
        const float* __restrict__ filt_W, const float* __restrict__ filt_b,
        const float* __restrict__ gate_W, const float* __restrict__ gate_b,
        const float* __restrict__ skip_W, const float* __restrict__ skip_b) {
    int nlayer = layer + 1;
    const float* Xres = flip ? g_XB : g_XA;
    float* Xout = flip ? g_XA : g_XB;
    __shared__ float s_xg[8*16*12], s_pp[8*16*12], s_qq[8*16*12], s_xn[8*16*12];
    __shared__ float wxT[256], wpT[256], wqT[256], swT[256];
    __shared__ float fw0T[256], fw1T[256], gw0T[256], gw1T[256];
    __shared__ float gcb[16], bnsc[16], bnsh[16], fb[16], gb[16], sb2[16];
    int tid = threadIdx.x;
    int vb0 = blockIdx.x * 8;
    for (int i = tid; i < 256; i += 256) {
        int c = i & 15, ci = i >> 4;
        wxT[i] = g_WX[layer*256 + c*16+ci];
        wpT[i] = g_WP[layer*256 + c*16+ci];
        wqT[i] = g_WQ[layer*256 + c*16+ci];
        swT[i] = skip_W[nlayer*256 + c*16+ci];
        fw0T[i] = filt_W[nlayer*512 + (c*16+ci)*2];
        fw1T[i] = filt_W[nlayer*512 + (c*16+ci)*2+1];
        gw0T[i] = gate_W[nlayer*512 + (c*16+ci)*2];
        gw1T[i] = gate_W[nlayer*512 + (c*16+ci)*2+1];
    }
    if (tid < 16) {
        gcb[tid]  = gconv_b[layer*16+tid];
        bnsc[tid] = g_bnsc[layer*16+tid];
        bnsh[tid] = g_bnsh[layer*16+tid];
        fb[tid]   = filt_b[nlayer*16+tid];
        gb[tid]   = gate_b[nlayer*16+tid];
        sb2[tid]  = skip_b[nlayer*16+tid];
    }
    {
        const float* srcX = g_XG + (size_t)vb0*16*Lout;
        const float* srcP = g_P  + (size_t)vb0*16*Lout;
        const float* srcQ = g_Q  + (size_t)vb0*16*Lout;
        int nload = 8*16*Lout;
        for (int i = tid; i < nload; i += 256) {
            int l = i % Lout, pc = i / Lout;
            s_xg[pc*12 + l] = srcX[i];
            s_pp[pc*12 + l] = srcP[i];
            s_qq[pc*12 + l] = srcQ[i];
        }
    }
    __syncthreads();
    for (int i = tid; i < 8*16*Lout; i += 256) {
        int l = i % Lout, pc = i / Lout, c = pc & 15, p = pc >> 4;
        float h = gcb[c];
        #pragma unroll
        for (int ci = 0; ci < 16; ci++) {
            int a = (p*16+ci)*12 + l;
            h += wxT[ci*16+c]*s_xg[a] + wpT[ci*16+c]*s_pp[a] + wqT[ci*16+c]*s_qq[a];
        }
        float res = Xres[(size_t)(vb0+p)*16*Lin + c*Lin + l + dil];
        float xv = (h + res) * bnsc[c] + bnsh[c];
        s_xn[pc*12 + l] = xv;
        if (layer < 6) Xout[(size_t)(vb0+p)*16*Lout + c*Lout + l] = xv;
    }
    __syncthreads();
    for (int i = tid; i < 8*16*nLout; i += 256) {
        int l = i % nLout, pc = i / nLout, c = pc & 15, p = pc >> 4;
        float f = fb[c], g = gb[c];
        #pragma unroll
        for (int ci = 0; ci < 16; ci++) {
            int a = (p*16+ci)*12 + l;
            float x0 = s_xn[a], x1 = s_xn[a + ndil];
            f += fw0T[ci*16+c]*x0 + fw1T[ci*16+c]*x1;
            g += gw0T[ci*16+c]*x0 + gw1T[ci*16+c]*x1;
        }
        float vv = tanhf(f) * sigm(g);
        s_xg[pc*12 + l] = vv;
        g_XG[(size_t)(vb0+p)*16*nLout + c*nLout + l] = vv;
    }
    __syncthreads();
    if (tid < 128) {
        int c = tid & 15, p = tid >> 4;
        float s = sb2[c];
        #pragma unroll
        for (int ci = 0; ci < 16; ci++) s += swT[ci*16+c] * s_xg[(p*16+ci)*12 + nLout - 1];
        g_skip[(size_t)(vb0+p)*16 + c] += s;
    }
}

// -------------------- end head : 16 pairs/block --------------------
__global__ __launch_bounds__(256) void end_kernel(const float* __restrict__ end1_W,
        const float* __restrict__ end1_b, const float* __restrict__ end2_W,
        const float* __restrict__ end2_b, float* __restrict__ out) {
    __shared__ float o1[16][16], o2[16][17];
    __shared__ float e1[256], e2[192], b1[16], b2[12];
    int tid = threadIdx.x;
    int vb0 = blockIdx.x * 16;
    for (int i = tid; i < 256; i += 256) e1[i] = end1_W[i];
    if (tid < 192) e2[tid] = end2_W[tid];
    if (tid < 16) b1[tid] = end1_b[tid];
    if (tid < 12) b2[tid] = end2_b[tid];
    int t = tid & 15, p = tid >> 4;
    o1[p][t] = fmaxf(g_skip[(size_t)(vb0+p)*16 + t], 0.f);
    __syncthreads();
    float a = b1[t];
    #pragma unroll
    for (int ci = 0; ci < 16; ci++) a += e1[t*16+ci] * o1[p][ci];
    o2[p][t] = fmaxf(a, 0.f);
    __syncthreads();
    if (t < HORC) {
        float r = b2[t];
        #pragma unroll
        for (int c = 0; c < 16; c++) r += e2[t*16+c] * o2[p][c];
        int vb = vb0 + p; int v = vb >> 5, b = vb & 31;
        out[((size_t)b*HORC + t)*VV + v] = r;
    }
}

// -------------------- launch --------------------
extern "C" void kernel_launch(void* const* d_in, const int* in_sizes, int n_in,
                              void* d_out, int out_size) {
    const float* input    = (const float*)d_in[0];
    const float* start_W  = (const float*)d_in[1];
    const float* start_b  = (const float*)d_in[2];
    const float* filt_W   = (const float*)d_in[3];
    const float* filt_b   = (const float*)d_in[4];
    const float* gate_W   = (const float*)d_in[5];
    const float* gate_b   = (const float*)d_in[6];
    const float* skip_W   = (const float*)d_in[7];
    const float* skip_b   = (const float*)d_in[8];
    const float* gconv_W  = (const float*)d_in[9];
    const float* gconv_b  = (const float*)d_in[10];
    const float* bn_gamma = (const float*)d_in[11];
    const float* bn_beta  = (const float*)d_in[12];
    const float* bn_mean  = (const float*)d_in[13];
    const float* bn_var   = (const float*)d_in[14];
    const float* end1_W   = (const float*)d_in[15];
    const float* end1_b   = (const float*)d_in[16];
    const float* end2_W   = (const float*)d_in[17];
    const float* end2_b   = (const float*)d_in[18];
    const float* lin_W    = (const float*)d_in[19];
    const float* lin_b    = (const float*)d_in[20];
    const float* fc1_W    = (const float*)d_in[21];
    const float* fc1_b    = (const float*)d_in[22];
    const float* fc2_W    = (const float*)d_in[23];
    const float* fc2_b    = (const float*)d_in[24];
    const float* fc3_W    = (const float*)d_in[25];
    const float* fc3_b    = (const float*)d_in[26];
    float* out = (float*)d_out;

    int do_copy = (out_size >= BB*HORC*VV + VV*VV) ? 1 : 0;

    setup_kernel<<<128, 256>>>(lin_W, fc1_W, fc1_b, fc2_W, fc2_b, fc3_W, fc3_b,
                               gconv_W, bn_gamma, bn_beta, bn_mean, bn_var);
    fftlin_kernel<<<BB*VV/128, 256>>>(input, lin_b);
    irfft2_kernel<<<dim3(8, BB), 256>>>();
    adj_part_kernel<<<dim3(VV/64, VV/32, 4), 256>>>();
    adj_finalize_kernel<<<dim3(16, 16), dim3(32, 8)>>>(out + BB*HORC*VV, do_copy);
    gemm_a2t<<<dim3(4, 4), 256>>>();
    start_gate_kernel<<<VV*BB/8, 256>>>(input, start_W, start_b,
                                        filt_W, filt_b, gate_W, gate_b, skip_W, skip_b);

    static const int dils[NLC] = {1, 2, 1, 2, 1, 2, 1, 2};
    int L = 13;
    int Lo = 12;
    for (int i = 0; i < 7; i++) {
        int N = BB * CHC * Lo;   // 512 * Lo
        gemm_layer_mma<<<dim3(N/64, 8), 256>>>(N);
        int nLo = Lo - dils[i+1];
        comb_gate_kernel<<<VV*BB/8, 256>>>(i, L, Lo, dils[i], i & 1, nLo, dils[i+1],
                                           gconv_b, filt_W, filt_b, gate_W, gate_b,
                                           skip_W, skip_b);
        L = Lo; Lo = nLo;
    }
    end_kernel<<<VV*BB/16, 256>>>(end1_W, end1_b, end2_W, end2_b, out);
}